// round 1
// baseline (speedup 1.0000x reference)
#include <cuda_runtime.h>
#include <math.h>

#define SEQ 2048
#define DIM 1024
#define NH 8
#define DFF 3072
#define EPSV 1e-5f

// ---------------- static device scratch (no runtime allocation) ----------------
__device__ float g_x[SEQ * DIM];                 // embeddings + PE
__device__ float g_q[NH * SEQ * DIM];
__device__ float g_k[NH * SEQ * DIM];
__device__ float g_v[NH * SEQ * DIM];
__device__ float g_scores[(size_t)NH * SEQ * SEQ];  // scores -> attn (in place)
__device__ float g_o[NH * SEQ * DIM];            // per-head attn @ V
__device__ float g_z[SEQ * DIM];                 // residual
__device__ float g_zn[SEQ * DIM];                // normalized
__device__ float g_ffh[SEQ * DFF];               // relu(zn@W1+b1)
__device__ double g_part[2 * 2048];              // per-block (sum, sumsq)
__device__ float g_stats[2];                     // mean, inv_std

// ---------------- embedding + sinusoidal positional encoding ----------------
__global__ void embed_pe_kernel(const int* __restrict__ tokens,
                                const float* __restrict__ emb) {
    int s = blockIdx.x;
    int tok = tokens[s];
    const float* erow = emb + (long long)tok * DIM;
    for (int d = threadIdx.x; d < DIM; d += blockDim.x) {
        int e = d & ~1;                              // 2*(d//2)
        float denom = powf(10000.0f, (float)e / (float)DIM);
        float angle = (float)s / denom;              // f32 like the reference
        // evaluate trig in double of the f32 angle: <=1ulp from ref value
        float pe = (d & 1) ? (float)cos((double)angle) : (float)sin((double)angle);
        g_x[s * DIM + d] = erow[d] + pe;
    }
}

// ---------------- tiled fp32 GEMM: C = alpha * A@B(^T) (+bias) (+relu) -------
// A: [M,K] row-major.  B: !TB -> [K,N] row-major;  TB -> [N,K] row-major.
// batched via blockIdx.z with element strides sA/sB/sBias/sC.
#define BM 128
#define BN 128
#define BK 8
#define TM 8
#define TN 8

template <bool TB, bool BIAS, bool RELU>
__global__ __launch_bounds__(256) void sgemm_kernel(
    const float* __restrict__ A, const float* __restrict__ B,
    const float* __restrict__ bias, float* __restrict__ C,
    int M, int N, int K,
    long long sA, long long sB, long long sBias, long long sC, float alpha) {
    __shared__ float As[BK][BM];
    __shared__ float Bs[BK][BN];

    const int b = blockIdx.z;
    A += (long long)b * sA;
    B += (long long)b * sB;
    C += (long long)b * sC;
    const float* bp = BIAS ? (bias + (long long)b * sBias) : nullptr;

    const int tid = threadIdx.x;
    const int blockRow = blockIdx.y * BM;
    const int blockCol = blockIdx.x * BN;

    // A tile loader: 128 rows x 8 cols, one float4 per thread
    const int aRow = tid >> 1;
    const int aCol = (tid & 1) * 4;
    // B tile loader (NN): 8 rows x 128 cols
    const int bRow = tid >> 5;
    const int bCol = (tid & 31) * 4;

    const int tx = tid & 15;
    const int ty = tid >> 4;

    float acc[TM][TN] = {};
    float regM[TM], regN[TN];

    for (int k0 = 0; k0 < K; k0 += BK) {
        float4 a4 = *(const float4*)(A + (long long)(blockRow + aRow) * K + k0 + aCol);
        As[aCol + 0][aRow] = a4.x;
        As[aCol + 1][aRow] = a4.y;
        As[aCol + 2][aRow] = a4.z;
        As[aCol + 3][aRow] = a4.w;
        if (TB) {
            float4 b4 = *(const float4*)(B + (long long)(blockCol + aRow) * K + k0 + aCol);
            Bs[aCol + 0][aRow] = b4.x;
            Bs[aCol + 1][aRow] = b4.y;
            Bs[aCol + 2][aRow] = b4.z;
            Bs[aCol + 3][aRow] = b4.w;
        } else {
            float4 b4 = *(const float4*)(B + (long long)(k0 + bRow) * N + blockCol + bCol);
            *(float4*)&Bs[bRow][bCol] = b4;
        }
        __syncthreads();
#pragma unroll
        for (int k = 0; k < BK; k++) {
#pragma unroll
            for (int i = 0; i < TM; i++) regM[i] = As[k][ty * TM + i];
#pragma unroll
            for (int j = 0; j < TN; j++) regN[j] = Bs[k][tx * TN + j];
#pragma unroll
            for (int i = 0; i < TM; i++)
#pragma unroll
                for (int j = 0; j < TN; j++) acc[i][j] += regM[i] * regN[j];
        }
        __syncthreads();
    }

#pragma unroll
    for (int i = 0; i < TM; i++) {
        long long row = blockRow + ty * TM + i;
#pragma unroll
        for (int j = 0; j < TN; j += 4) {
            int col = blockCol + tx * TN + j;
            float4 v;
            v.x = acc[i][j + 0] * alpha;
            v.y = acc[i][j + 1] * alpha;
            v.z = acc[i][j + 2] * alpha;
            v.w = acc[i][j + 3] * alpha;
            if (BIAS) {
                v.x += bp[col + 0];
                v.y += bp[col + 1];
                v.z += bp[col + 2];
                v.w += bp[col + 3];
            }
            if (RELU) {
                v.x = fmaxf(v.x, 0.f);
                v.y = fmaxf(v.y, 0.f);
                v.z = fmaxf(v.z, 0.f);
                v.w = fmaxf(v.w, 0.f);
            }
            *(float4*)(C + row * N + col) = v;
        }
    }
}

// ---------------- row softmax over 2048 columns (one block per row) ----------
__global__ __launch_bounds__(256) void softmax_kernel() {
    long long row = blockIdx.x;
    float* p = g_scores + row * SEQ;
    const int tid = threadIdx.x;

    float4 a = ((const float4*)p)[tid * 2 + 0];
    float4 b = ((const float4*)p)[tid * 2 + 1];

    float m = fmaxf(fmaxf(fmaxf(a.x, a.y), fmaxf(a.z, a.w)),
                    fmaxf(fmaxf(b.x, b.y), fmaxf(b.z, b.w)));
    __shared__ float red[256];
    red[tid] = m;
    __syncthreads();
    for (int o = 128; o > 0; o >>= 1) {
        if (tid < o) red[tid] = fmaxf(red[tid], red[tid + o]);
        __syncthreads();
    }
    m = red[0];
    __syncthreads();

    a.x = expf(a.x - m); a.y = expf(a.y - m); a.z = expf(a.z - m); a.w = expf(a.w - m);
    b.x = expf(b.x - m); b.y = expf(b.y - m); b.z = expf(b.z - m); b.w = expf(b.w - m);
    float s = a.x + a.y + a.z + a.w + b.x + b.y + b.z + b.w;
    red[tid] = s;
    __syncthreads();
    for (int o = 128; o > 0; o >>= 1) {
        if (tid < o) red[tid] += red[tid + o];
        __syncthreads();
    }
    float inv = 1.0f / red[0];
    a.x *= inv; a.y *= inv; a.z *= inv; a.w *= inv;
    b.x *= inv; b.y *= inv; b.z *= inv; b.w *= inv;
    ((float4*)p)[tid * 2 + 0] = a;
    ((float4*)p)[tid * 2 + 1] = b;
}

// -------- head-sum + residual; per-block double (sum, sumsq) partials --------
__global__ __launch_bounds__(256) void residual_reduce_kernel() {
    const int tid = threadIdx.x;
    long long base = (long long)blockIdx.x * 1024;
    double s = 0.0, ss = 0.0;
#pragma unroll
    for (int it = 0; it < 4; it++) {
        long long idx = base + tid + it * 256;
        float acc = g_x[idx];
#pragma unroll
        for (int h = 0; h < NH; h++) acc += g_o[(long long)h * SEQ * DIM + idx];
        g_z[idx] = acc;
        s += acc;
        ss += (double)acc * acc;
    }
    __shared__ double sh[256], sh2[256];
    sh[tid] = s;
    sh2[tid] = ss;
    __syncthreads();
    for (int o = 128; o > 0; o >>= 1) {
        if (tid < o) { sh[tid] += sh[tid + o]; sh2[tid] += sh2[tid + o]; }
        __syncthreads();
    }
    if (tid == 0) {
        g_part[blockIdx.x * 2 + 0] = sh[0];
        g_part[blockIdx.x * 2 + 1] = sh2[0];
    }
}

__global__ __launch_bounds__(256) void finalize_stats_kernel() {
    const int tid = threadIdx.x;
    double s = 0.0, ss = 0.0;
    for (int i = tid; i < 2048; i += 256) {
        s += g_part[2 * i + 0];
        ss += g_part[2 * i + 1];
    }
    __shared__ double sh[256], sh2[256];
    sh[tid] = s;
    sh2[tid] = ss;
    __syncthreads();
    for (int o = 128; o > 0; o >>= 1) {
        if (tid < o) { sh[tid] += sh[tid + o]; sh2[tid] += sh2[tid + o]; }
        __syncthreads();
    }
    if (tid == 0) {
        double n = (double)SEQ * DIM;
        double mean = sh[0] / n;
        double var = sh2[0] / n - mean * mean;
        g_stats[0] = (float)mean;
        g_stats[1] = (float)(1.0 / sqrt(var + (double)EPSV));
    }
}

__global__ __launch_bounds__(256) void normalize_kernel() {
    float mean = g_stats[0];
    float inv = g_stats[1];
    long long idx = ((long long)blockIdx.x * 256 + threadIdx.x) * 4;
    float4 v = *(const float4*)&g_z[idx];
    v.x = (v.x - mean) * inv;
    v.y = (v.y - mean) * inv;
    v.z = (v.z - mean) * inv;
    v.w = (v.w - mean) * inv;
    *(float4*)&g_zn[idx] = v;
}

// --------------------------------- launch ------------------------------------
extern "C" void kernel_launch(void* const* d_in, const int* in_sizes, int n_in,
                              void* d_out, int out_size) {
    const int* tokens = (const int*)d_in[0];
    const float* emb = (const float*)d_in[1];
    const float* Wq = (const float*)d_in[2];
    const float* bq = (const float*)d_in[3];
    const float* Wk = (const float*)d_in[4];
    const float* bk = (const float*)d_in[5];
    const float* Wv = (const float*)d_in[6];
    const float* bv = (const float*)d_in[7];
    const float* W1 = (const float*)d_in[8];
    const float* b1 = (const float*)d_in[9];
    const float* W2 = (const float*)d_in[10];
    const float* b2 = (const float*)d_in[11];
    float* out = (float*)d_out;

    float *x, *q, *k, *v, *sc, *o, *zn, *ffh;
    cudaGetSymbolAddress((void**)&x, g_x);
    cudaGetSymbolAddress((void**)&q, g_q);
    cudaGetSymbolAddress((void**)&k, g_k);
    cudaGetSymbolAddress((void**)&v, g_v);
    cudaGetSymbolAddress((void**)&sc, g_scores);
    cudaGetSymbolAddress((void**)&o, g_o);
    cudaGetSymbolAddress((void**)&zn, g_zn);
    cudaGetSymbolAddress((void**)&ffh, g_ffh);

    dim3 blk(256);

    embed_pe_kernel<<<SEQ, 256>>>(tokens, emb);

    // Q/K/V projections: per-head GEMM x[S,D] @ W[h][D,D] + b[h]
    {
        dim3 grid(DIM / BN, SEQ / BM, NH);
        sgemm_kernel<false, true, false><<<grid, blk>>>(
            x, Wq, bq, q, SEQ, DIM, DIM, 0, (long long)DIM * DIM, DIM,
            (long long)SEQ * DIM, 1.0f);
        sgemm_kernel<false, true, false><<<grid, blk>>>(
            x, Wk, bk, k, SEQ, DIM, DIM, 0, (long long)DIM * DIM, DIM,
            (long long)SEQ * DIM, 1.0f);
        sgemm_kernel<false, true, false><<<grid, blk>>>(
            x, Wv, bv, v, SEQ, DIM, DIM, 0, (long long)DIM * DIM, DIM,
            (long long)SEQ * DIM, 1.0f);
    }

    // scores = Q @ K^T / sqrt(D)
    {
        dim3 grid(SEQ / BN, SEQ / BM, NH);
        sgemm_kernel<true, false, false><<<grid, blk>>>(
            q, k, nullptr, sc, SEQ, SEQ, DIM, (long long)SEQ * DIM,
            (long long)SEQ * DIM, 0, (long long)SEQ * SEQ, 1.0f / 32.0f);
    }

    softmax_kernel<<<NH * SEQ, 256>>>();

    // per-head O = attn @ V
    {
        dim3 grid(DIM / BN, SEQ / BM, NH);
        sgemm_kernel<false, false, false><<<grid, blk>>>(
            sc, v, nullptr, o, SEQ, DIM, SEQ, (long long)SEQ * SEQ,
            (long long)SEQ * DIM, 0, (long long)SEQ * DIM, 1.0f);
    }

    residual_reduce_kernel<<<2048, 256>>>();
    finalize_stats_kernel<<<1, 256>>>();
    normalize_kernel<<<2048, 256>>>();

    // FFN
    {
        dim3 grid(DFF / BN, SEQ / BM, 1);
        sgemm_kernel<false, true, true><<<grid, blk>>>(
            zn, W1, b1, ffh, SEQ, DFF, DIM, 0, 0, 0, 0, 1.0f);
    }
    {
        dim3 grid(DIM / BN, SEQ / BM, 1);
        sgemm_kernel<false, true, false><<<grid, blk>>>(
            ffh, W2, b2, out, SEQ, DIM, DFF, 0, 0, 0, 0, 1.0f);
    }
}

// round 2
// speedup vs baseline: 2.1278x; 2.1278x over previous
#include <cuda_runtime.h>
#include <cuda_bf16.h>
#include <math.h>
#include <stdint.h>

#define SEQ 2048
#define DIM 1024
#define NH 8
#define DFF 3072
#define EPSV 1e-5f

// ---------------- static device scratch (no runtime allocation) ----------------
__device__ float g_x[SEQ * DIM];                 // embeddings + PE
__device__ float g_q[NH * SEQ * DIM];
__device__ float g_k[NH * SEQ * DIM];
__device__ float g_v[NH * SEQ * DIM];
__device__ float g_scores[(size_t)NH * SEQ * SEQ];  // scores -> attn (in place)
__device__ float g_o[NH * SEQ * DIM];            // per-head attn @ V
__device__ float g_z[SEQ * DIM];                 // residual
__device__ float g_zn[SEQ * DIM];                // normalized
__device__ float g_ffh[SEQ * DFF];               // relu(zn@W1+b1)
__device__ double g_part[2 * 2048];              // per-block (sum, sumsq)
__device__ float g_stats[2];                     // mean, inv_std

// ---------------- embedding + sinusoidal positional encoding ----------------
__global__ void embed_pe_kernel(const int* __restrict__ tokens,
                                const float* __restrict__ emb) {
    int s = blockIdx.x;
    int tok = tokens[s];
    const float* erow = emb + (long long)tok * DIM;
    for (int d = threadIdx.x; d < DIM; d += blockDim.x) {
        int e = d & ~1;
        float denom = powf(10000.0f, (float)e / (float)DIM);
        float angle = (float)s / denom;
        float pe = (d & 1) ? (float)cos((double)angle) : (float)sin((double)angle);
        g_x[s * DIM + d] = erow[d] + pe;
    }
}

// =================== bf16-split tensor-core GEMM ===========================
// C = alpha * A@B(^T) (+bias) (+relu), fp32 in/out, HMMA bf16 with hi/lo
// error compensation: C ~= Ahi*Bhi + Ahi*Blo + Alo*Bhi  (rel err ~2^-18)
//
// Block tile 128x128x32, 256 threads (8 warps), warp tile 32(M) x 64(N).
// smem: hi/lo tiles for A and B, k-major rows, pitch 18 words (conflict-free),
// double buffered.

#define BM 128
#define BN 128
#define BKE 32                  // K elements per tile
#define PITCH 18                // 32-bit words per row (16 data + 2 pad)
#define MAT_WORDS (128 * PITCH) // words per matrix part per stage
#define STAGE_WORDS (4 * MAT_WORDS)
#define SMEM_BYTES (2 * STAGE_WORDS * 4)

__device__ __forceinline__ void split2(float x, float y, uint32_t& h, uint32_t& l) {
    __nv_bfloat16 bx = __float2bfloat16_rn(x);
    __nv_bfloat16 by = __float2bfloat16_rn(y);
    __nv_bfloat162 hv;
    hv.x = bx; hv.y = by;
    h = *reinterpret_cast<uint32_t*>(&hv);
    float rx = x - __bfloat162float(bx);
    float ry = y - __bfloat162float(by);
    __nv_bfloat162 lv = __floats2bfloat162_rn(rx, ry);
    l = *reinterpret_cast<uint32_t*>(&lv);
}

#define MMA_BF16(d, a, b)                                                      \
    asm volatile(                                                              \
        "mma.sync.aligned.m16n8k16.row.col.f32.bf16.bf16.f32 "                 \
        "{%0,%1,%2,%3},{%4,%5,%6,%7},{%8,%9},{%0,%1,%2,%3};"                   \
        : "+f"(d[0]), "+f"(d[1]), "+f"(d[2]), "+f"(d[3])                       \
        : "r"(a[0]), "r"(a[1]), "r"(a[2]), "r"(a[3]), "r"(b[0]), "r"(b[1]))

template <bool TB, bool BIAS, bool RELU>
__global__ __launch_bounds__(256) void bgemm_kernel(
    const float* __restrict__ A, const float* __restrict__ B,
    const float* __restrict__ bias, float* __restrict__ C,
    int M, int N, int K,
    long long sA, long long sB, long long sBias, long long sC, float alpha) {
    extern __shared__ uint32_t smem[];

    const int b = blockIdx.z;
    A += (long long)b * sA;
    B += (long long)b * sB;
    C += (long long)b * sC;
    const float* bp = BIAS ? (bias + (long long)b * sBias) : nullptr;

    const int tid = threadIdx.x;
    const int lane = tid & 31;
    const int warp = tid >> 5;
    const int wm = warp & 3;   // warp row (M), 0..3
    const int wn = warp >> 2;  // warp col (N), 0..1
    const int blockRow = blockIdx.y * BM;
    const int blockCol = blockIdx.x * BN;

    float acc[2][8][4];
#pragma unroll
    for (int i = 0; i < 2; i++)
#pragma unroll
        for (int j = 0; j < 8; j++)
#pragma unroll
            for (int r = 0; r < 4; r++) acc[i][j][r] = 0.0f;

    // ---- loader register staging ----
    float4 ra[4];      // A tile: 4 float4 per thread (k-contiguous)
    float4 rbt[4];     // B tile TB path (k-contiguous, like A)
    float rbn[16];     // B tile NN path: one n-column, 16 k values

    const int aRow = tid >> 3;          // 0..31 (+32*i)
    const int aC4 = tid & 7;            // float4 within 32-k row
    const int bnN = tid & 127;          // NN path: n within tile
    const int bnKh = (tid >> 7) * 16;   // NN path: k chunk base (0 or 16)

    const int nIter = K / BKE;

    auto loadA = [&](int k0) {
#pragma unroll
        for (int i = 0; i < 4; i++) {
            int row = aRow + i * 32;
            ra[i] = *(const float4*)(A + (long long)(blockRow + row) * K + k0 + aC4 * 4);
        }
    };
    auto loadB = [&](int k0) {
        if (TB) {
#pragma unroll
            for (int i = 0; i < 4; i++) {
                int row = aRow + i * 32;
                rbt[i] = *(const float4*)(B + (long long)(blockCol + row) * K + k0 + aC4 * 4);
            }
        } else {
#pragma unroll
            for (int j = 0; j < 16; j++) {
                rbn[j] = B[(long long)(k0 + bnKh + j) * N + blockCol + bnN];
            }
        }
    };
    auto storeA = [&](int st) {
        uint32_t* hi = smem + st * STAGE_WORDS;
        uint32_t* lo = hi + MAT_WORDS;
#pragma unroll
        for (int i = 0; i < 4; i++) {
            int row = aRow + i * 32;
            int off = row * PITCH + aC4 * 2;
            uint32_t h0, l0, h1, l1;
            split2(ra[i].x, ra[i].y, h0, l0);
            split2(ra[i].z, ra[i].w, h1, l1);
            hi[off] = h0; hi[off + 1] = h1;
            lo[off] = l0; lo[off + 1] = l1;
        }
    };
    auto storeB = [&](int st) {
        uint32_t* hi = smem + st * STAGE_WORDS + 2 * MAT_WORDS;
        uint32_t* lo = hi + MAT_WORDS;
        if (TB) {
#pragma unroll
            for (int i = 0; i < 4; i++) {
                int row = aRow + i * 32;
                int off = row * PITCH + aC4 * 2;
                uint32_t h0, l0, h1, l1;
                split2(rbt[i].x, rbt[i].y, h0, l0);
                split2(rbt[i].z, rbt[i].w, h1, l1);
                hi[off] = h0; hi[off + 1] = h1;
                lo[off] = l0; lo[off + 1] = l1;
            }
        } else {
#pragma unroll
            for (int j = 0; j < 8; j++) {
                uint32_t h, l;
                split2(rbn[2 * j], rbn[2 * j + 1], h, l);
                int off = bnN * PITCH + (bnKh >> 1) + j;
                hi[off] = h;
                lo[off] = l;
            }
        }
    };

    // prologue
    loadA(0);
    loadB(0);
    storeA(0);
    storeB(0);
    __syncthreads();

    for (int t = 0; t < nIter; t++) {
        const int st = t & 1;
        if (t + 1 < nIter) {
            loadA((t + 1) * BKE);
            loadB((t + 1) * BKE);
        }
        // ---- compute from stage st ----
        {
            const uint32_t* aH = smem + st * STAGE_WORDS;
            const uint32_t* aL = aH + MAT_WORDS;
            const uint32_t* bH = aH + 2 * MAT_WORDS;
            const uint32_t* bL = aH + 3 * MAT_WORDS;
#pragma unroll
            for (int ks = 0; ks < 2; ks++) {
                const int kw = (lane & 3) + ks * 8;
                uint32_t ah[2][4], al[2][4];
#pragma unroll
                for (int mf = 0; mf < 2; mf++) {
                    int r = wm * 32 + mf * 16 + (lane >> 2);
                    ah[mf][0] = aH[r * PITCH + kw];
                    ah[mf][1] = aH[(r + 8) * PITCH + kw];
                    ah[mf][2] = aH[r * PITCH + kw + 4];
                    ah[mf][3] = aH[(r + 8) * PITCH + kw + 4];
                    al[mf][0] = aL[r * PITCH + kw];
                    al[mf][1] = aL[(r + 8) * PITCH + kw];
                    al[mf][2] = aL[r * PITCH + kw + 4];
                    al[mf][3] = aL[(r + 8) * PITCH + kw + 4];
                }
                uint32_t bh[8][2], bl[8][2];
#pragma unroll
                for (int nf = 0; nf < 8; nf++) {
                    int c = wn * 64 + nf * 8 + (lane >> 2);
                    bh[nf][0] = bH[c * PITCH + kw];
                    bh[nf][1] = bH[c * PITCH + kw + 4];
                    bl[nf][0] = bL[c * PITCH + kw];
                    bl[nf][1] = bL[c * PITCH + kw + 4];
                }
#pragma unroll
                for (int mf = 0; mf < 2; mf++)
#pragma unroll
                    for (int nf = 0; nf < 8; nf++) {
                        MMA_BF16(acc[mf][nf], ah[mf], bh[nf]);
                        MMA_BF16(acc[mf][nf], ah[mf], bl[nf]);
                        MMA_BF16(acc[mf][nf], al[mf], bh[nf]);
                    }
            }
        }
        if (t + 1 < nIter) {
            storeA(st ^ 1);
            storeB(st ^ 1);
            __syncthreads();
        }
    }

    // ---- epilogue ----
#pragma unroll
    for (int mf = 0; mf < 2; mf++) {
        int r0 = blockRow + wm * 32 + mf * 16 + (lane >> 2);
#pragma unroll
        for (int nf = 0; nf < 8; nf++) {
            int c0 = blockCol + wn * 64 + nf * 8 + (lane & 3) * 2;
            float2 v0, v1;
            v0.x = acc[mf][nf][0] * alpha;
            v0.y = acc[mf][nf][1] * alpha;
            v1.x = acc[mf][nf][2] * alpha;
            v1.y = acc[mf][nf][3] * alpha;
            if (BIAS) {
                float b0 = bp[c0], b1 = bp[c0 + 1];
                v0.x += b0; v0.y += b1;
                v1.x += b0; v1.y += b1;
            }
            if (RELU) {
                v0.x = fmaxf(v0.x, 0.f); v0.y = fmaxf(v0.y, 0.f);
                v1.x = fmaxf(v1.x, 0.f); v1.y = fmaxf(v1.y, 0.f);
            }
            *(float2*)(C + (long long)r0 * N + c0) = v0;
            *(float2*)(C + (long long)(r0 + 8) * N + c0) = v1;
        }
    }
}

// ---------------- row softmax over 2048 columns (one block per row) ----------
__global__ __launch_bounds__(256) void softmax_kernel() {
    long long row = blockIdx.x;
    float* p = g_scores + row * SEQ;
    const int tid = threadIdx.x;

    float4 a = ((const float4*)p)[tid * 2 + 0];
    float4 b = ((const float4*)p)[tid * 2 + 1];

    float m = fmaxf(fmaxf(fmaxf(a.x, a.y), fmaxf(a.z, a.w)),
                    fmaxf(fmaxf(b.x, b.y), fmaxf(b.z, b.w)));
    __shared__ float red[256];
    red[tid] = m;
    __syncthreads();
    for (int o = 128; o > 0; o >>= 1) {
        if (tid < o) red[tid] = fmaxf(red[tid], red[tid + o]);
        __syncthreads();
    }
    m = red[0];
    __syncthreads();

    a.x = expf(a.x - m); a.y = expf(a.y - m); a.z = expf(a.z - m); a.w = expf(a.w - m);
    b.x = expf(b.x - m); b.y = expf(b.y - m); b.z = expf(b.z - m); b.w = expf(b.w - m);
    float s = a.x + a.y + a.z + a.w + b.x + b.y + b.z + b.w;
    red[tid] = s;
    __syncthreads();
    for (int o = 128; o > 0; o >>= 1) {
        if (tid < o) red[tid] += red[tid + o];
        __syncthreads();
    }
    float inv = 1.0f / red[0];
    a.x *= inv; a.y *= inv; a.z *= inv; a.w *= inv;
    b.x *= inv; b.y *= inv; b.z *= inv; b.w *= inv;
    ((float4*)p)[tid * 2 + 0] = a;
    ((float4*)p)[tid * 2 + 1] = b;
}

// -------- head-sum + residual; per-block double (sum, sumsq) partials --------
__global__ __launch_bounds__(256) void residual_reduce_kernel() {
    const int tid = threadIdx.x;
    long long base = (long long)blockIdx.x * 1024;
    double s = 0.0, ss = 0.0;
#pragma unroll
    for (int it = 0; it < 4; it++) {
        long long idx = base + tid + it * 256;
        float acc = g_x[idx];
#pragma unroll
        for (int h = 0; h < NH; h++) acc += g_o[(long long)h * SEQ * DIM + idx];
        g_z[idx] = acc;
        s += acc;
        ss += (double)acc * acc;
    }
    __shared__ double sh[256], sh2[256];
    sh[tid] = s;
    sh2[tid] = ss;
    __syncthreads();
    for (int o = 128; o > 0; o >>= 1) {
        if (tid < o) { sh[tid] += sh[tid + o]; sh2[tid] += sh2[tid + o]; }
        __syncthreads();
    }
    if (tid == 0) {
        g_part[blockIdx.x * 2 + 0] = sh[0];
        g_part[blockIdx.x * 2 + 1] = sh2[0];
    }
}

__global__ __launch_bounds__(256) void finalize_stats_kernel() {
    const int tid = threadIdx.x;
    double s = 0.0, ss = 0.0;
    for (int i = tid; i < 2048; i += 256) {
        s += g_part[2 * i + 0];
        ss += g_part[2 * i + 1];
    }
    __shared__ double sh[256], sh2[256];
    sh[tid] = s;
    sh2[tid] = ss;
    __syncthreads();
    for (int o = 128; o > 0; o >>= 1) {
        if (tid < o) { sh[tid] += sh[tid + o]; sh2[tid] += sh2[tid + o]; }
        __syncthreads();
    }
    if (tid == 0) {
        double n = (double)SEQ * DIM;
        double mean = sh[0] / n;
        double var = sh2[0] / n - mean * mean;
        g_stats[0] = (float)mean;
        g_stats[1] = (float)(1.0 / sqrt(var + (double)EPSV));
    }
}

__global__ __launch_bounds__(256) void normalize_kernel() {
    float mean = g_stats[0];
    float inv = g_stats[1];
    long long idx = ((long long)blockIdx.x * 256 + threadIdx.x) * 4;
    float4 v = *(const float4*)&g_z[idx];
    v.x = (v.x - mean) * inv;
    v.y = (v.y - mean) * inv;
    v.z = (v.z - mean) * inv;
    v.w = (v.w - mean) * inv;
    *(float4*)&g_zn[idx] = v;
}

// --------------------------------- launch ------------------------------------
extern "C" void kernel_launch(void* const* d_in, const int* in_sizes, int n_in,
                              void* d_out, int out_size) {
    const int* tokens = (const int*)d_in[0];
    const float* emb = (const float*)d_in[1];
    const float* Wq = (const float*)d_in[2];
    const float* bq = (const float*)d_in[3];
    const float* Wk = (const float*)d_in[4];
    const float* bk = (const float*)d_in[5];
    const float* Wv = (const float*)d_in[6];
    const float* bv = (const float*)d_in[7];
    const float* W1 = (const float*)d_in[8];
    const float* b1 = (const float*)d_in[9];
    const float* W2 = (const float*)d_in[10];
    const float* b2 = (const float*)d_in[11];
    float* out = (float*)d_out;

    float *x, *q, *k, *v, *sc, *o, *zn, *ffh;
    cudaGetSymbolAddress((void**)&x, g_x);
    cudaGetSymbolAddress((void**)&q, g_q);
    cudaGetSymbolAddress((void**)&k, g_k);
    cudaGetSymbolAddress((void**)&v, g_v);
    cudaGetSymbolAddress((void**)&sc, g_scores);
    cudaGetSymbolAddress((void**)&o, g_o);
    cudaGetSymbolAddress((void**)&zn, g_zn);
    cudaGetSymbolAddress((void**)&ffh, g_ffh);

    cudaFuncSetAttribute(bgemm_kernel<false, true, false>,
                         cudaFuncAttributeMaxDynamicSharedMemorySize, SMEM_BYTES);
    cudaFuncSetAttribute(bgemm_kernel<true, false, false>,
                         cudaFuncAttributeMaxDynamicSharedMemorySize, SMEM_BYTES);
    cudaFuncSetAttribute(bgemm_kernel<false, false, false>,
                         cudaFuncAttributeMaxDynamicSharedMemorySize, SMEM_BYTES);
    cudaFuncSetAttribute(bgemm_kernel<false, true, true>,
                         cudaFuncAttributeMaxDynamicSharedMemorySize, SMEM_BYTES);

    dim3 blk(256);

    embed_pe_kernel<<<SEQ, 256>>>(tokens, emb);

    // Q/K/V projections: per-head GEMM x[S,D] @ W[h][D,D] + b[h]
    {
        dim3 grid(DIM / BN, SEQ / BM, NH);
        bgemm_kernel<false, true, false><<<grid, blk, SMEM_BYTES>>>(
            x, Wq, bq, q, SEQ, DIM, DIM, 0, (long long)DIM * DIM, DIM,
            (long long)SEQ * DIM, 1.0f);
        bgemm_kernel<false, true, false><<<grid, blk, SMEM_BYTES>>>(
            x, Wk, bk, k, SEQ, DIM, DIM, 0, (long long)DIM * DIM, DIM,
            (long long)SEQ * DIM, 1.0f);
        bgemm_kernel<false, true, false><<<grid, blk, SMEM_BYTES>>>(
            x, Wv, bv, v, SEQ, DIM, DIM, 0, (long long)DIM * DIM, DIM,
            (long long)SEQ * DIM, 1.0f);
    }

    // scores = Q @ K^T / sqrt(D)
    {
        dim3 grid(SEQ / BN, SEQ / BM, NH);
        bgemm_kernel<true, false, false><<<grid, blk, SMEM_BYTES>>>(
            q, k, nullptr, sc, SEQ, SEQ, DIM, (long long)SEQ * DIM,
            (long long)SEQ * DIM, 0, (long long)SEQ * SEQ, 1.0f / 32.0f);
    }

    softmax_kernel<<<NH * SEQ, 256>>>();

    // per-head O = attn @ V
    {
        dim3 grid(DIM / BN, SEQ / BM, NH);
        bgemm_kernel<false, false, false><<<grid, blk, SMEM_BYTES>>>(
            sc, v, nullptr, o, SEQ, DIM, SEQ, (long long)SEQ * SEQ,
            (long long)SEQ * DIM, 0, (long long)SEQ * DIM, 1.0f);
    }

    residual_reduce_kernel<<<2048, 256>>>();
    finalize_stats_kernel<<<1, 256>>>();
    normalize_kernel<<<2048, 256>>>();

    // FFN
    {
        dim3 grid(DFF / BN, SEQ / BM, 1);
        bgemm_kernel<false, true, true><<<grid, blk, SMEM_BYTES>>>(
            zn, W1, b1, ffh, SEQ, DFF, DIM, 0, 0, 0, 0, 1.0f);
    }
    {
        dim3 grid(DIM / BN, SEQ / BM, 1);
        bgemm_kernel<false, true, false><<<grid, blk, SMEM_BYTES>>>(
            ffh, W2, b2, out, SEQ, DIM, DFF, 0, 0, 0, 0, 1.0f);
    }
}

// round 3
// speedup vs baseline: 2.7271x; 1.2817x over previous
#include <cuda_runtime.h>
#include <cuda_bf16.h>
#include <math.h>
#include <stdint.h>

#define SEQ 2048
#define DIM 1024
#define NH 8
#define DFF 3072
#define EPSV 1e-5f

// ---------------- static device scratch ----------------
__device__ __align__(128) float g_x[SEQ * DIM];
__device__ __align__(128) __nv_bfloat16 g_xh[SEQ * DIM], g_xl[SEQ * DIM];
__device__ __align__(128) __nv_bfloat16 g_qh[NH * SEQ * DIM], g_ql[NH * SEQ * DIM];
__device__ __align__(128) __nv_bfloat16 g_kh[NH * SEQ * DIM], g_kl[NH * SEQ * DIM];
__device__ __align__(128) float g_v[NH * SEQ * DIM];
__device__ __align__(128) __nv_bfloat16 g_vth[NH * SEQ * DIM], g_vtl[NH * SEQ * DIM];
__device__ __align__(128) float g_scores[(size_t)NH * SEQ * SEQ];
__device__ __align__(128) __nv_bfloat16 g_ah_[(size_t)NH * SEQ * SEQ];
__device__ __align__(128) __nv_bfloat16 g_al_[(size_t)NH * SEQ * SEQ];
__device__ __align__(128) float g_o[NH * SEQ * DIM];
__device__ __align__(128) float g_z[SEQ * DIM];
__device__ __align__(128) __nv_bfloat16 g_znh[SEQ * DIM], g_znl[SEQ * DIM];
__device__ __align__(128) __nv_bfloat16 g_ffhh[SEQ * DFF], g_ffhl[SEQ * DFF];
// transposed split weights
__device__ __align__(128) __nv_bfloat16 g_wqth[NH * DIM * DIM], g_wqtl[NH * DIM * DIM];
__device__ __align__(128) __nv_bfloat16 g_wkth[NH * DIM * DIM], g_wktl[NH * DIM * DIM];
__device__ __align__(128) __nv_bfloat16 g_wvth[NH * DIM * DIM], g_wvtl[NH * DIM * DIM];
__device__ __align__(128) __nv_bfloat16 g_w1th[DFF * DIM], g_w1tl[DFF * DIM];
__device__ __align__(128) __nv_bfloat16 g_w2th[DIM * DFF], g_w2tl[DIM * DFF];
__device__ double g_part[2 * 2048];
__device__ float g_stats[2];

// ---------------- helpers ----------------
__device__ __forceinline__ void split2(float x, float y, uint32_t& h, uint32_t& l) {
    __nv_bfloat16 bx = __float2bfloat16_rn(x);
    __nv_bfloat16 by = __float2bfloat16_rn(y);
    __nv_bfloat162 hv;
    hv.x = bx; hv.y = by;
    h = *reinterpret_cast<uint32_t*>(&hv);
    __nv_bfloat162 lv = __floats2bfloat162_rn(x - __bfloat162float(bx),
                                              y - __bfloat162float(by));
    l = *reinterpret_cast<uint32_t*>(&lv);
}

__device__ __forceinline__ void cp16(uint32_t d, const void* s) {
    asm volatile("cp.async.cg.shared.global [%0], [%1], 16;" :: "r"(d), "l"(s));
}

#define LDSM4(R0, R1, R2, R3, ADDR)                                            \
    asm volatile("ldmatrix.sync.aligned.m8n8.x4.shared.b16 {%0,%1,%2,%3}, [%4];" \
                 : "=r"(R0), "=r"(R1), "=r"(R2), "=r"(R3) : "r"(ADDR))

#define MMA_BF16(d, a, b)                                                      \
    asm volatile(                                                              \
        "mma.sync.aligned.m16n8k16.row.col.f32.bf16.bf16.f32 "                 \
        "{%0,%1,%2,%3},{%4,%5,%6,%7},{%8,%9},{%0,%1,%2,%3};"                   \
        : "+f"(d[0]), "+f"(d[1]), "+f"(d[2]), "+f"(d[3])                       \
        : "r"(a[0]), "r"(a[1]), "r"(a[2]), "r"(a[3]), "r"(b[0]), "r"(b[1]))

// ---------------- embedding + PE ----------------
__global__ void embed_pe_kernel(const int* __restrict__ tokens,
                                const float* __restrict__ emb) {
    int s = blockIdx.x;
    int tok = tokens[s];
    const float* erow = emb + (long long)tok * DIM;
    for (int d = threadIdx.x; d < DIM; d += blockDim.x) {
        int e = d & ~1;
        float denom = powf(10000.0f, (float)e / (float)DIM);
        float angle = (float)s / denom;
        float pe = (d & 1) ? (float)cos((double)angle) : (float)sin((double)angle);
        g_x[s * DIM + d] = erow[d] + pe;
    }
}

// ---------------- elementwise split fp32 -> bf16 hi/lo ----------------
__global__ __launch_bounds__(256) void split_kernel(const float* __restrict__ in,
                                                    __nv_bfloat16* __restrict__ oh,
                                                    __nv_bfloat16* __restrict__ ol) {
    long long i = ((long long)blockIdx.x * 256 + threadIdx.x) * 4;
    float4 v = *(const float4*)(in + i);
    uint32_t h0, l0, h1, l1;
    split2(v.x, v.y, h0, l0);
    split2(v.z, v.w, h1, l1);
    uint2 hh = make_uint2(h0, h1), ll = make_uint2(l0, l1);
    *(uint2*)(oh + i) = hh;
    *(uint2*)(ol + i) = ll;
}

// ---------------- transpose + split: in[R,C] fp32 -> out[C,R] bf16 hi/lo ------
__global__ __launch_bounds__(256) void tsplit_kernel(
    const float* __restrict__ in, __nv_bfloat16* __restrict__ oh,
    __nv_bfloat16* __restrict__ ol, int R, int C, long long sIn, long long sOut) {
    __shared__ float t[32][33];
    int z = blockIdx.z;
    in += (long long)z * sIn;
    oh += (long long)z * sOut;
    ol += (long long)z * sOut;
    int c0 = blockIdx.x * 32, r0 = blockIdx.y * 32;
    int tx = threadIdx.x, ty = threadIdx.y;  // 32 x 8
#pragma unroll
    for (int j = 0; j < 4; j++)
        t[ty + j * 8][tx] = in[(long long)(r0 + ty + j * 8) * C + c0 + tx];
    __syncthreads();
#pragma unroll
    for (int j = 0; j < 4; j++) {
        float v = t[tx][ty + j * 8];
        int orow = c0 + ty + j * 8;
        int ocol = r0 + tx;
        __nv_bfloat16 h = __float2bfloat16_rn(v);
        oh[(long long)orow * R + ocol] = h;
        ol[(long long)orow * R + ocol] = __float2bfloat16_rn(v - __bfloat162float(h));
    }
}

// =================== bf16-split tensor-core GEMM (TN) =======================
// C[M,N] = alpha * A[M,K] @ B[N,K]^T  (+bias) (+relu), A/B given as bf16 hi/lo.
// Block 128x128xBK32, 256 threads, warp tile 64x32. 3-stage cp.async pipeline,
// ldmatrix fragment loads, swizzled smem (128B rows = 32 hi + 32 lo bf16).

#define STAGES 3
#define STAGE_BYTES 32768    // 16KB A + 16KB B

template <bool BIAS, bool RELU, bool SPLITOUT>
__global__ __launch_bounds__(256) void tgemm(
    const __nv_bfloat16* __restrict__ Ah, const __nv_bfloat16* __restrict__ Al,
    const __nv_bfloat16* __restrict__ Bh, const __nv_bfloat16* __restrict__ Bl,
    const float* __restrict__ bias, float* __restrict__ C,
    __nv_bfloat16* __restrict__ Ch, __nv_bfloat16* __restrict__ Cl,
    int M, int N, int K,
    long long sA, long long sB, long long sBias, long long sC, float alpha) {
    extern __shared__ char smem[];
    uint32_t sbase;
    asm("{ .reg .u64 t; cvta.to.shared.u64 t, %1; cvt.u32.u64 %0, t; }"
        : "=r"(sbase) : "l"(smem));

    const int z = blockIdx.z;
    Ah += (long long)z * sA; Al += (long long)z * sA;
    Bh += (long long)z * sB; Bl += (long long)z * sB;
    const float* bp = BIAS ? (bias + (long long)z * sBias) : nullptr;
    const long long cOff = (long long)z * sC;

    const int tid = threadIdx.x;
    const int lane = tid & 31;
    const int warp = tid >> 5;
    const int wm = warp >> 2;   // 0..1 -> 64 rows
    const int wn = warp & 3;    // 0..3 -> 32 cols
    const int blockRow = blockIdx.y * 128;
    const int blockCol = blockIdx.x * 128;

    // ---- cp.async per-thread source pointers & dst offsets ----
    const __nv_bfloat16* srcA[4];
    const __nv_bfloat16* srcB[4];
    uint32_t dstA[4], dstB[4];
#pragma unroll
    for (int i = 0; i < 4; i++) {
        int idx = i * 256 + tid;
        int row = idx >> 3;
        int sub = idx & 7;
        int part = sub >> 2;
        int cc = sub & 3;
        uint32_t chunk = (uint32_t)(((part << 2) | cc) ^ (row & 7));
        dstA[i] = (uint32_t)(row * 128) + (chunk << 4);
        dstB[i] = dstA[i] + 16384u;
        srcA[i] = (part ? Al : Ah) + (long long)(blockRow + row) * K + cc * 8;
        srcB[i] = (part ? Bl : Bh) + (long long)(blockCol + row) * K + cc * 8;
    }

    // ---- ldmatrix per-thread swizzled offsets (ks=0, hi) ----
    uint32_t aoff[4], boff[2];
    {
        int kh = lane >> 4;
#pragma unroll
        for (int mf = 0; mf < 4; mf++) {
            int r = wm * 64 + mf * 16 + (lane & 15);
            aoff[mf] = (uint32_t)(r * 128) + ((uint32_t)(kh ^ (r & 7)) << 4);
        }
        int khb = (lane >> 3) & 1;
#pragma unroll
        for (int ng = 0; ng < 2; ng++) {
            int n = wn * 32 + ng * 16 + ((lane >> 4) << 3) + (lane & 7);
            boff[ng] = (uint32_t)(n * 128) + ((uint32_t)(khb ^ (n & 7)) << 4) + 16384u;
        }
    }

    float acc[4][4][4];
#pragma unroll
    for (int a = 0; a < 4; a++)
#pragma unroll
        for (int b = 0; b < 4; b++)
#pragma unroll
            for (int r = 0; r < 4; r++) acc[a][b][r] = 0.0f;

    const int nIter = K / 32;

    auto load_stage = [&](int s, int k0) {
        uint32_t base = sbase + s * STAGE_BYTES;
#pragma unroll
        for (int i = 0; i < 4; i++) cp16(base + dstA[i], srcA[i] + k0);
#pragma unroll
        for (int i = 0; i < 4; i++) cp16(base + dstB[i], srcB[i] + k0);
        asm volatile("cp.async.commit_group;");
    };

#pragma unroll
    for (int s = 0; s < STAGES - 1; s++) load_stage(s, s * 32);

    for (int t = 0; t < nIter; t++) {
        asm volatile("cp.async.wait_group %0;" :: "n"(STAGES - 2));
        __syncthreads();
        const int s = t % STAGES;
        const int tn = t + STAGES - 1;
        if (tn < nIter) load_stage(tn % STAGES, tn * 32);
        else asm volatile("cp.async.commit_group;");

        const uint32_t stBase = sbase + s * STAGE_BYTES;
#pragma unroll
        for (int ks = 0; ks < 2; ks++) {
            const uint32_t kx = ks ? 32u : 0u;
            uint32_t ah[4][4], al[4][4], bh[4][2], bl[4][2];
#pragma unroll
            for (int mf = 0; mf < 4; mf++) {
                uint32_t ad = stBase + (aoff[mf] ^ kx);
                LDSM4(ah[mf][0], ah[mf][1], ah[mf][2], ah[mf][3], ad);
                LDSM4(al[mf][0], al[mf][1], al[mf][2], al[mf][3], ad ^ 64u);
            }
#pragma unroll
            for (int ng = 0; ng < 2; ng++) {
                uint32_t bd = stBase + (boff[ng] ^ kx);
                LDSM4(bh[2 * ng][0], bh[2 * ng][1], bh[2 * ng + 1][0],
                      bh[2 * ng + 1][1], bd);
                LDSM4(bl[2 * ng][0], bl[2 * ng][1], bl[2 * ng + 1][0],
                      bl[2 * ng + 1][1], bd ^ 64u);
            }
#pragma unroll
            for (int mf = 0; mf < 4; mf++)
#pragma unroll
                for (int nf = 0; nf < 4; nf++) {
                    MMA_BF16(acc[mf][nf], ah[mf], bh[nf]);
                    MMA_BF16(acc[mf][nf], ah[mf], bl[nf]);
                    MMA_BF16(acc[mf][nf], al[mf], bh[nf]);
                }
        }
        __syncthreads();
    }

    // ---- epilogue ----
#pragma unroll
    for (int mf = 0; mf < 4; mf++) {
        int row = blockRow + wm * 64 + mf * 16 + (lane >> 2);
#pragma unroll
        for (int nf = 0; nf < 4; nf++) {
            int col = blockCol + wn * 32 + nf * 8 + (lane & 3) * 2;
            float2 v0, v1;
            v0.x = acc[mf][nf][0] * alpha;
            v0.y = acc[mf][nf][1] * alpha;
            v1.x = acc[mf][nf][2] * alpha;
            v1.y = acc[mf][nf][3] * alpha;
            if (BIAS) {
                float b0 = bp[col], b1 = bp[col + 1];
                v0.x += b0; v0.y += b1;
                v1.x += b0; v1.y += b1;
            }
            if (RELU) {
                v0.x = fmaxf(v0.x, 0.f); v0.y = fmaxf(v0.y, 0.f);
                v1.x = fmaxf(v1.x, 0.f); v1.y = fmaxf(v1.y, 0.f);
            }
            if (SPLITOUT) {
                uint32_t h, l;
                split2(v0.x, v0.y, h, l);
                *(uint32_t*)(Ch + cOff + (long long)row * N + col) = h;
                *(uint32_t*)(Cl + cOff + (long long)row * N + col) = l;
                split2(v1.x, v1.y, h, l);
                *(uint32_t*)(Ch + cOff + (long long)(row + 8) * N + col) = h;
                *(uint32_t*)(Cl + cOff + (long long)(row + 8) * N + col) = l;
            } else {
                *(float2*)(C + cOff + (long long)row * N + col) = v0;
                *(float2*)(C + cOff + (long long)(row + 8) * N + col) = v1;
            }
        }
    }
}

// ---------------- row softmax + split write ----------------
__global__ __launch_bounds__(256) void softmax_kernel() {
    long long row = blockIdx.x;
    float* p = g_scores + row * SEQ;
    const int tid = threadIdx.x;

    float4 a = ((const float4*)p)[tid * 2 + 0];
    float4 b = ((const float4*)p)[tid * 2 + 1];

    float m = fmaxf(fmaxf(fmaxf(a.x, a.y), fmaxf(a.z, a.w)),
                    fmaxf(fmaxf(b.x, b.y), fmaxf(b.z, b.w)));
    __shared__ float red[256];
    red[tid] = m;
    __syncthreads();
    for (int o = 128; o > 0; o >>= 1) {
        if (tid < o) red[tid] = fmaxf(red[tid], red[tid + o]);
        __syncthreads();
    }
    m = red[0];
    __syncthreads();

    a.x = expf(a.x - m); a.y = expf(a.y - m); a.z = expf(a.z - m); a.w = expf(a.w - m);
    b.x = expf(b.x - m); b.y = expf(b.y - m); b.z = expf(b.z - m); b.w = expf(b.w - m);
    float s = a.x + a.y + a.z + a.w + b.x + b.y + b.z + b.w;
    red[tid] = s;
    __syncthreads();
    for (int o = 128; o > 0; o >>= 1) {
        if (tid < o) red[tid] += red[tid + o];
        __syncthreads();
    }
    float inv = 1.0f / red[0];
    a.x *= inv; a.y *= inv; a.z *= inv; a.w *= inv;
    b.x *= inv; b.y *= inv; b.z *= inv; b.w *= inv;

    uint32_t h0, l0, h1, l1, h2, l2, h3, l3;
    split2(a.x, a.y, h0, l0);
    split2(a.z, a.w, h1, l1);
    split2(b.x, b.y, h2, l2);
    split2(b.z, b.w, h3, l3);
    uint4 hh = make_uint4(h0, h1, h2, h3);
    uint4 ll = make_uint4(l0, l1, l2, l3);
    ((uint4*)(g_ah_ + row * SEQ))[tid] = hh;
    ((uint4*)(g_al_ + row * SEQ))[tid] = ll;
}

// -------- head-sum + residual; double (sum, sumsq) partials --------
__global__ __launch_bounds__(256) void residual_reduce_kernel() {
    const int tid = threadIdx.x;
    long long base = (long long)blockIdx.x * 1024;
    double s = 0.0, ss = 0.0;
#pragma unroll
    for (int it = 0; it < 4; it++) {
        long long idx = base + tid + it * 256;
        float acc = g_x[idx];
#pragma unroll
        for (int h = 0; h < NH; h++) acc += g_o[(long long)h * SEQ * DIM + idx];
        g_z[idx] = acc;
        s += acc;
        ss += (double)acc * acc;
    }
    __shared__ double sh[256], sh2[256];
    sh[tid] = s; sh2[tid] = ss;
    __syncthreads();
    for (int o = 128; o > 0; o >>= 1) {
        if (tid < o) { sh[tid] += sh[tid + o]; sh2[tid] += sh2[tid + o]; }
        __syncthreads();
    }
    if (tid == 0) {
        g_part[blockIdx.x * 2 + 0] = sh[0];
        g_part[blockIdx.x * 2 + 1] = sh2[0];
    }
}

__global__ __launch_bounds__(256) void finalize_stats_kernel() {
    const int tid = threadIdx.x;
    double s = 0.0, ss = 0.0;
    for (int i = tid; i < 2048; i += 256) {
        s += g_part[2 * i + 0];
        ss += g_part[2 * i + 1];
    }
    __shared__ double sh[256], sh2[256];
    sh[tid] = s; sh2[tid] = ss;
    __syncthreads();
    for (int o = 128; o > 0; o >>= 1) {
        if (tid < o) { sh[tid] += sh[tid + o]; sh2[tid] += sh2[tid + o]; }
        __syncthreads();
    }
    if (tid == 0) {
        double n = (double)SEQ * DIM;
        double mean = sh[0] / n;
        double var = sh2[0] / n - mean * mean;
        g_stats[0] = (float)mean;
        g_stats[1] = (float)(1.0 / sqrt(var + (double)EPSV));
    }
}

__global__ __launch_bounds__(256) void normalize_kernel() {
    float mean = g_stats[0];
    float inv = g_stats[1];
    long long idx = ((long long)blockIdx.x * 256 + threadIdx.x) * 4;
    float4 v = *(const float4*)&g_z[idx];
    v.x = (v.x - mean) * inv;
    v.y = (v.y - mean) * inv;
    v.z = (v.z - mean) * inv;
    v.w = (v.w - mean) * inv;
    uint32_t h0, l0, h1, l1;
    split2(v.x, v.y, h0, l0);
    split2(v.z, v.w, h1, l1);
    *(uint2*)(g_znh + idx) = make_uint2(h0, h1);
    *(uint2*)(g_znl + idx) = make_uint2(l0, l1);
}

// --------------------------------- launch ------------------------------------
extern "C" void kernel_launch(void* const* d_in, const int* in_sizes, int n_in,
                              void* d_out, int out_size) {
    const int* tokens = (const int*)d_in[0];
    const float* emb = (const float*)d_in[1];
    const float* Wq = (const float*)d_in[2];
    const float* bq = (const float*)d_in[3];
    const float* Wk = (const float*)d_in[4];
    const float* bk = (const float*)d_in[5];
    const float* Wv = (const float*)d_in[6];
    const float* bv = (const float*)d_in[7];
    const float* W1 = (const float*)d_in[8];
    const float* b1 = (const float*)d_in[9];
    const float* W2 = (const float*)d_in[10];
    const float* b2 = (const float*)d_in[11];
    float* out = (float*)d_out;

    // symbol addresses
    float *x, *v, *sc, *o;
    __nv_bfloat16 *xh, *xl, *qh, *ql, *kh, *kl, *vth, *vtl, *ah, *al;
    __nv_bfloat16 *znh, *znl, *ffhh, *ffhl;
    __nv_bfloat16 *wqth, *wqtl, *wkth, *wktl, *wvth, *wvtl, *w1th, *w1tl, *w2th, *w2tl;
    cudaGetSymbolAddress((void**)&x, g_x);
    cudaGetSymbolAddress((void**)&v, g_v);
    cudaGetSymbolAddress((void**)&sc, g_scores);
    cudaGetSymbolAddress((void**)&o, g_o);
    cudaGetSymbolAddress((void**)&xh, g_xh);
    cudaGetSymbolAddress((void**)&xl, g_xl);
    cudaGetSymbolAddress((void**)&qh, g_qh);
    cudaGetSymbolAddress((void**)&ql, g_ql);
    cudaGetSymbolAddress((void**)&kh, g_kh);
    cudaGetSymbolAddress((void**)&kl, g_kl);
    cudaGetSymbolAddress((void**)&vth, g_vth);
    cudaGetSymbolAddress((void**)&vtl, g_vtl);
    cudaGetSymbolAddress((void**)&ah, g_ah_);
    cudaGetSymbolAddress((void**)&al, g_al_);
    cudaGetSymbolAddress((void**)&znh, g_znh);
    cudaGetSymbolAddress((void**)&znl, g_znl);
    cudaGetSymbolAddress((void**)&ffhh, g_ffhh);
    cudaGetSymbolAddress((void**)&ffhl, g_ffhl);
    cudaGetSymbolAddress((void**)&wqth, g_wqth);
    cudaGetSymbolAddress((void**)&wqtl, g_wqtl);
    cudaGetSymbolAddress((void**)&wkth, g_wkth);
    cudaGetSymbolAddress((void**)&wktl, g_wktl);
    cudaGetSymbolAddress((void**)&wvth, g_wvth);
    cudaGetSymbolAddress((void**)&wvtl, g_wvtl);
    cudaGetSymbolAddress((void**)&w1th, g_w1th);
    cudaGetSymbolAddress((void**)&w1tl, g_w1tl);
    cudaGetSymbolAddress((void**)&w2th, g_w2th);
    cudaGetSymbolAddress((void**)&w2tl, g_w2tl);

    const int SMEM = STAGES * STAGE_BYTES;
    cudaFuncSetAttribute(tgemm<true, false, true>,
                         cudaFuncAttributeMaxDynamicSharedMemorySize, SMEM);
    cudaFuncSetAttribute(tgemm<true, false, false>,
                         cudaFuncAttributeMaxDynamicSharedMemorySize, SMEM);
    cudaFuncSetAttribute(tgemm<false, false, false>,
                         cudaFuncAttributeMaxDynamicSharedMemorySize, SMEM);
    cudaFuncSetAttribute(tgemm<true, true, true>,
                         cudaFuncAttributeMaxDynamicSharedMemorySize, SMEM);

    embed_pe_kernel<<<SEQ, 256>>>(tokens, emb);
    split_kernel<<<SEQ * DIM / 1024, 256>>>(x, xh, xl);

    // weight transpose-splits
    {
        dim3 tb(32, 8);
        tsplit_kernel<<<dim3(32, 32, 8), tb>>>(Wq, wqth, wqtl, DIM, DIM,
                                               (long long)DIM * DIM, (long long)DIM * DIM);
        tsplit_kernel<<<dim3(32, 32, 8), tb>>>(Wk, wkth, wktl, DIM, DIM,
                                               (long long)DIM * DIM, (long long)DIM * DIM);
        tsplit_kernel<<<dim3(32, 32, 8), tb>>>(Wv, wvth, wvtl, DIM, DIM,
                                               (long long)DIM * DIM, (long long)DIM * DIM);
        tsplit_kernel<<<dim3(DFF / 32, DIM / 32, 1), tb>>>(W1, w1th, w1tl, DIM, DFF, 0, 0);
        tsplit_kernel<<<dim3(DIM / 32, DFF / 32, 1), tb>>>(W2, w2th, w2tl, DFF, DIM, 0, 0);
    }

    // Q,K projections -> split outputs
    {
        dim3 grid(DIM / 128, SEQ / 128, NH);
        tgemm<true, false, true><<<grid, 256, SMEM>>>(
            xh, xl, wqth, wqtl, bq, nullptr, qh, ql, SEQ, DIM, DIM,
            0, (long long)DIM * DIM, DIM, (long long)SEQ * DIM, 1.0f);
        tgemm<true, false, true><<<grid, 256, SMEM>>>(
            xh, xl, wkth, wktl, bk, nullptr, kh, kl, SEQ, DIM, DIM,
            0, (long long)DIM * DIM, DIM, (long long)SEQ * DIM, 1.0f);
        // V -> fp32, then transpose-split
        tgemm<true, false, false><<<grid, 256, SMEM>>>(
            xh, xl, wvth, wvtl, bv, v, nullptr, nullptr, SEQ, DIM, DIM,
            0, (long long)DIM * DIM, DIM, (long long)SEQ * DIM, 1.0f);
        tsplit_kernel<<<dim3(DIM / 32, SEQ / 32, NH), dim3(32, 8)>>>(
            v, vth, vtl, SEQ, DIM, (long long)SEQ * DIM, (long long)SEQ * DIM);
    }

    // scores = Q @ K^T / 32
    {
        dim3 grid(SEQ / 128, SEQ / 128, NH);
        tgemm<false, false, false><<<grid, 256, SMEM>>>(
            qh, ql, kh, kl, nullptr, sc, nullptr, nullptr, SEQ, SEQ, DIM,
            (long long)SEQ * DIM, (long long)SEQ * DIM, 0,
            (long long)SEQ * SEQ, 1.0f / 32.0f);
    }

    softmax_kernel<<<NH * SEQ, 256>>>();

    // O = attn @ V
    {
        dim3 grid(DIM / 128, SEQ / 128, NH);
        tgemm<false, false, false><<<grid, 256, SMEM>>>(
            ah, al, vth, vtl, nullptr, o, nullptr, nullptr, SEQ, DIM, SEQ,
            (long long)SEQ * SEQ, (long long)SEQ * DIM, 0,
            (long long)SEQ * DIM, 1.0f);
    }

    residual_reduce_kernel<<<2048, 256>>>();
    finalize_stats_kernel<<<1, 256>>>();
    normalize_kernel<<<2048, 256>>>();

    // FFN1: relu(zn @ W1 + b1) -> split
    {
        dim3 grid(DFF / 128, SEQ / 128, 1);
        tgemm<true, true, true><<<grid, 256, SMEM>>>(
            znh, znl, w1th, w1tl, b1, nullptr, ffhh, ffhl, SEQ, DFF, DIM,
            0, 0, 0, 0, 1.0f);
    }
    // FFN2: ffh @ W2 + b2 -> out
    {
        dim3 grid(DIM / 128, SEQ / 128, 1);
        tgemm<true, false, false><<<grid, 256, SMEM>>>(
            ffhh, ffhl, w2th, w2tl, b2, out, nullptr, nullptr, SEQ, DIM, DFF,
            0, 0, 0, 0, 1.0f);
    }
}

// round 5
// speedup vs baseline: 5.1261x; 1.8797x over previous
#include <cuda_runtime.h>
#include <cuda_bf16.h>
#include <math.h>
#include <stdint.h>

#define SEQ 2048
#define DIM 1024
#define NH 8
#define DFF 3072
#define EPSV 1e-5f

// tcgen05 only exists on the arch-specific target pass (sm_103a / sm_100a).
#if defined(__CUDA_ARCH_FEAT_SM103_ALL) || defined(__CUDA_ARCH_FEAT_SM100_ALL)
#define HAS_TCGEN05 1
#else
#define HAS_TCGEN05 0
#endif

// ---------------- static device scratch ----------------
__device__ __align__(128) float g_x[SEQ * DIM];
__device__ __align__(128) __nv_bfloat16 g_xh[SEQ * DIM], g_xl[SEQ * DIM];
__device__ __align__(128) __nv_bfloat16 g_qh[NH * SEQ * DIM], g_ql[NH * SEQ * DIM];
__device__ __align__(128) __nv_bfloat16 g_kh[NH * SEQ * DIM], g_kl[NH * SEQ * DIM];
__device__ __align__(128) float g_v[NH * SEQ * DIM];
__device__ __align__(128) __nv_bfloat16 g_vth[NH * SEQ * DIM], g_vtl[NH * SEQ * DIM];
__device__ __align__(128) float g_scores[(size_t)NH * SEQ * SEQ];
__device__ __align__(128) __nv_bfloat16 g_ah_[(size_t)NH * SEQ * SEQ];
__device__ __align__(128) __nv_bfloat16 g_al_[(size_t)NH * SEQ * SEQ];
__device__ __align__(128) float g_o[NH * SEQ * DIM];
__device__ __align__(128) float g_z[SEQ * DIM];
__device__ __align__(128) __nv_bfloat16 g_znh[SEQ * DIM], g_znl[SEQ * DIM];
__device__ __align__(128) __nv_bfloat16 g_ffhh[SEQ * DFF], g_ffhl[SEQ * DFF];
__device__ __align__(128) __nv_bfloat16 g_wqth[NH * DIM * DIM], g_wqtl[NH * DIM * DIM];
__device__ __align__(128) __nv_bfloat16 g_wkth[NH * DIM * DIM], g_wktl[NH * DIM * DIM];
__device__ __align__(128) __nv_bfloat16 g_wvth[NH * DIM * DIM], g_wvtl[NH * DIM * DIM];
__device__ __align__(128) __nv_bfloat16 g_w1th[DFF * DIM], g_w1tl[DFF * DIM];
__device__ __align__(128) __nv_bfloat16 g_w2th[DIM * DFF], g_w2tl[DIM * DFF];
__device__ double g_part[2 * 2048];
__device__ float g_stats[2];

// ---------------- helpers ----------------
__device__ __forceinline__ void split2(float x, float y, uint32_t& h, uint32_t& l) {
    __nv_bfloat16 bx = __float2bfloat16_rn(x);
    __nv_bfloat16 by = __float2bfloat16_rn(y);
    __nv_bfloat162 hv;
    hv.x = bx; hv.y = by;
    h = *reinterpret_cast<uint32_t*>(&hv);
    __nv_bfloat162 lv = __floats2bfloat162_rn(x - __bfloat162float(bx),
                                              y - __bfloat162float(by));
    l = *reinterpret_cast<uint32_t*>(&lv);
}

__device__ __forceinline__ void cp16(uint32_t d, const void* s) {
    asm volatile("cp.async.cg.shared.global [%0], [%1], 16;" :: "r"(d), "l"(s));
}

__device__ __forceinline__ uint32_t smem_u32(const void* p) {
    uint32_t a;
    asm("{ .reg .u64 t; cvta.to.shared.u64 t, %1; cvt.u32.u64 %0, t; }"
        : "=r"(a) : "l"(p));
    return a;
}

__device__ __forceinline__ uint32_t elect_one() {
    uint32_t pred;
    asm volatile(
        "{\n\t.reg .pred p;\n\telect.sync _|p, 0xFFFFFFFF;\n\t"
        "selp.b32 %0, 1, 0, p;\n\t}" : "=r"(pred));
    return pred;
}

#define MBAR_INIT(addr, cnt) \
    asm volatile("mbarrier.init.shared.b64 [%0], %1;" :: "r"(addr), "r"(cnt) : "memory")

#define MBAR_WAIT(addr, par) do {                                              \
    uint32_t _m = (addr), _p = (par), _d;                                      \
    asm volatile(                                                              \
        "{\n\t.reg .pred p;\n\t"                                               \
        "mbarrier.try_wait.parity.acquire.cta.shared::cta.b64 p, [%1], %2;\n\t" \
        "selp.b32 %0, 1, 0, p;\n\t}" : "=r"(_d) : "r"(_m), "r"(_p) : "memory"); \
    if (!_d) {                                                                 \
        asm volatile(                                                          \
            "{\n\t.reg .pred P1;\n\t"                                          \
            "WL_%=:\n\t"                                                       \
            "mbarrier.try_wait.parity.acquire.cta.shared::cta.b64 P1, [%0], %1, 0x989680;\n\t" \
            "@P1 bra.uni WD_%=;\n\tbra.uni WL_%=;\n\tWD_%=:\n\t}"              \
            :: "r"(_m), "r"(_p) : "memory");                                   \
    }                                                                          \
} while (0)

// mma.sync fallback primitives (compute_103-safe)
#define LDSM4(R0, R1, R2, R3, ADDR)                                            \
    asm volatile("ldmatrix.sync.aligned.m8n8.x4.shared.b16 {%0,%1,%2,%3}, [%4];" \
                 : "=r"(R0), "=r"(R1), "=r"(R2), "=r"(R3) : "r"(ADDR))

#define MMA_SYNC_BF16(d, a, b)                                                 \
    asm volatile(                                                              \
        "mma.sync.aligned.m16n8k16.row.col.f32.bf16.bf16.f32 "                 \
        "{%0,%1,%2,%3},{%4,%5,%6,%7},{%8,%9},{%0,%1,%2,%3};"                   \
        : "+f"(d[0]), "+f"(d[1]), "+f"(d[2]), "+f"(d[3])                       \
        : "r"(a[0]), "r"(a[1]), "r"(a[2]), "r"(a[3]), "r"(b[0]), "r"(b[1]))

// tcgen05 macros (only expanded inside the guarded branch)
#define TC_ALLOC(addr, n)                                                      \
    asm volatile("tcgen05.alloc.cta_group::1.sync.aligned.shared::cta.b32 [%0], %1;" \
                 :: "r"(addr), "r"(n) : "memory")
#define TC_DEALLOC(t, n) \
    asm volatile("tcgen05.dealloc.cta_group::1.sync.aligned.b32 %0, %1;" :: "r"(t), "r"(n))
#define TC_RELINQ() \
    asm volatile("tcgen05.relinquish_alloc_permit.cta_group::1.sync.aligned;")
#define TC_FENCE_AFTER() asm volatile("tcgen05.fence::after_thread_sync;" ::: "memory")
#define TC_FENCE_BEFORE() asm volatile("tcgen05.fence::before_thread_sync;" ::: "memory")
#define TC_WAIT_LD() asm volatile("tcgen05.wait::ld.sync.aligned;" ::: "memory")
#define FENCE_ASYNC() asm volatile("fence.proxy.async.shared::cta;" ::: "memory")
#define TC_COMMIT(addr)                                                        \
    asm volatile(                                                              \
        "tcgen05.commit.cta_group::1.mbarrier::arrive::one.shared::cluster.b64 [%0];" \
        :: "r"(addr) : "memory")
#define TC_MMA_F16(d, a, b, idesc, en)                                         \
    asm volatile(                                                              \
        "{\n\t.reg .pred p;\n\tsetp.ne.u32 p, %4, 0;\n\t"                      \
        "tcgen05.mma.cta_group::1.kind::f16 [%0], %1, %2, %3, {%5,%5,%5,%5}, p;\n\t}" \
        :: "r"(d), "l"(a), "l"(b), "r"(idesc), "r"(en), "r"(0u) : "memory")
#define TC_LD_X32(r, a)                                                        \
    asm volatile(                                                              \
        "tcgen05.ld.sync.aligned.32x32b.x32.b32 "                              \
        "{%0, %1, %2, %3, %4, %5, %6, %7, "                                    \
        " %8, %9, %10, %11, %12, %13, %14, %15, "                              \
        " %16, %17, %18, %19, %20, %21, %22, %23, "                            \
        " %24, %25, %26, %27, %28, %29, %30, %31}, [%32];"                     \
        : "=r"((r)[0]),  "=r"((r)[1]),  "=r"((r)[2]),  "=r"((r)[3]),           \
          "=r"((r)[4]),  "=r"((r)[5]),  "=r"((r)[6]),  "=r"((r)[7]),           \
          "=r"((r)[8]),  "=r"((r)[9]),  "=r"((r)[10]), "=r"((r)[11]),          \
          "=r"((r)[12]), "=r"((r)[13]), "=r"((r)[14]), "=r"((r)[15]),          \
          "=r"((r)[16]), "=r"((r)[17]), "=r"((r)[18]), "=r"((r)[19]),          \
          "=r"((r)[20]), "=r"((r)[21]), "=r"((r)[22]), "=r"((r)[23]),          \
          "=r"((r)[24]), "=r"((r)[25]), "=r"((r)[26]), "=r"((r)[27]),          \
          "=r"((r)[28]), "=r"((r)[29]), "=r"((r)[30]), "=r"((r)[31])           \
        : "r"(a))

// SW128 K-major descriptor: LBO=1 (16B), SBO=64 (1024B), version=1, layout=2
#define DESC_BASE_SW128                                                        \
    ((uint64_t(2) << 61) | (uint64_t(1) << 46) | (uint64_t(64) << 32) |        \
     (uint64_t(1) << 16))
#define MAKE_DESC(addr) (DESC_BASE_SW128 | ((uint64_t)((addr) >> 4) & 0x3FFF))
#define IDESC_128 0x8200490u  // f32 acc, bf16 a/b, N=128, M=128

// ---------------- embedding + PE ----------------
__global__ void embed_pe_kernel(const int* __restrict__ tokens,
                                const float* __restrict__ emb) {
    int s = blockIdx.x;
    int tok = tokens[s];
    const float* erow = emb + (long long)tok * DIM;
    for (int d = threadIdx.x; d < DIM; d += blockDim.x) {
        int e = d & ~1;
        float denom = powf(10000.0f, (float)e / (float)DIM);
        float angle = (float)s / denom;
        float pe = (d & 1) ? (float)cos((double)angle) : (float)sin((double)angle);
        g_x[s * DIM + d] = erow[d] + pe;
    }
}

// ---------------- elementwise split fp32 -> bf16 hi/lo ----------------
__global__ __launch_bounds__(256) void split_kernel(const float* __restrict__ in,
                                                    __nv_bfloat16* __restrict__ oh,
                                                    __nv_bfloat16* __restrict__ ol) {
    long long i = ((long long)blockIdx.x * 256 + threadIdx.x) * 4;
    float4 v = *(const float4*)(in + i);
    uint32_t h0, l0, h1, l1;
    split2(v.x, v.y, h0, l0);
    split2(v.z, v.w, h1, l1);
    *(uint2*)(oh + i) = make_uint2(h0, h1);
    *(uint2*)(ol + i) = make_uint2(l0, l1);
}

// ---------------- transpose + split ----------------
__global__ __launch_bounds__(256) void tsplit_kernel(
    const float* __restrict__ in, __nv_bfloat16* __restrict__ oh,
    __nv_bfloat16* __restrict__ ol, int R, int C, long long sIn, long long sOut) {
    __shared__ float t[32][33];
    int z = blockIdx.z;
    in += (long long)z * sIn;
    oh += (long long)z * sOut;
    ol += (long long)z * sOut;
    int c0 = blockIdx.x * 32, r0 = blockIdx.y * 32;
    int tx = threadIdx.x, ty = threadIdx.y;
#pragma unroll
    for (int j = 0; j < 4; j++)
        t[ty + j * 8][tx] = in[(long long)(r0 + ty + j * 8) * C + c0 + tx];
    __syncthreads();
#pragma unroll
    for (int j = 0; j < 4; j++) {
        float v = t[tx][ty + j * 8];
        int orow = c0 + ty + j * 8;
        int ocol = r0 + tx;
        __nv_bfloat16 h = __float2bfloat16_rn(v);
        oh[(long long)orow * R + ocol] = h;
        ol[(long long)orow * R + ocol] = __float2bfloat16_rn(v - __bfloat162float(h));
    }
}

// =================== bf16-split GEMM (TN): tcgen05 or mma.sync ==============
// C[M,N] = alpha * A[M,K] @ B[N,K]^T (+bias)(+relu), 3-term bf16 hi/lo.
// 256 threads. tcgen05 path: CTA 128x128, K-chunk 64, 3-stage cp.async ring,
// single 128-col TMEM accumulator. Fallback (non-'a' pass): R3 mma.sync body.

#define TSTAGE_BYTES 65536
#define TSMEM_BYTES (3 * TSTAGE_BYTES + 1024)
#define FB_STAGE_BYTES 32768

template <bool BIAS, bool RELU, bool SPLITOUT>
__global__ __launch_bounds__(256) void tgemm(
    const __nv_bfloat16* __restrict__ Ah, const __nv_bfloat16* __restrict__ Al,
    const __nv_bfloat16* __restrict__ Bh, const __nv_bfloat16* __restrict__ Bl,
    const float* __restrict__ bias, float* __restrict__ C,
    __nv_bfloat16* __restrict__ Ch, __nv_bfloat16* __restrict__ Cl,
    int M, int N, int K,
    long long sA, long long sB, long long sBias, long long sC, float alpha) {
    extern __shared__ char smem[];

    const int z = blockIdx.z;
    Ah += (long long)z * sA; Al += (long long)z * sA;
    Bh += (long long)z * sB; Bl += (long long)z * sB;
    const float* bp = BIAS ? (bias + (long long)z * sBias) : nullptr;
    const long long cOff = (long long)z * sC;

    const int tid = threadIdx.x;
    const int lane = tid & 31;
    const int warp = tid >> 5;
    const int blockRow = blockIdx.y * 128;
    const int blockCol = blockIdx.x * 128;

#if HAS_TCGEN05
    // ======================= tcgen05 path (sm_103a) ==========================
    __shared__ __align__(8) unsigned long long s_mbar[3];
    __shared__ uint32_t s_tmem[1];
    const uint32_t sb0 = (smem_u32(smem) + 1023u) & ~1023u;
    const uint32_t mb0 = smem_u32(s_mbar);

    if (warp == 0) TC_ALLOC(smem_u32(s_tmem), 128);
    if (tid == 0) {
        MBAR_INIT(mb0 + 0, 1);
        MBAR_INIT(mb0 + 8, 1);
        MBAR_INIT(mb0 + 16, 1);
    }
    __syncthreads();
    const uint32_t tmem = s_tmem[0];

    const int nIter = K / 64;

    auto load_stage = [&](int buf, int k0) {
        uint32_t base = sb0 + buf * TSTAGE_BYTES;
#pragma unroll
        for (int i = 0; i < 4; i++) {
            int idx = i * 256 + tid;
            int row = idx >> 3;
            int c = idx & 7;
            uint32_t d0 = base + (uint32_t)(row * 128) + ((uint32_t)(c ^ (row & 7)) << 4);
            long long ga = (long long)(blockRow + row) * K + k0 + c * 8;
            long long gb = (long long)(blockCol + row) * K + k0 + c * 8;
            cp16(d0, Ah + ga);
            cp16(d0 + 16384u, Al + ga);
            cp16(d0 + 32768u, Bh + gb);
            cp16(d0 + 49152u, Bl + gb);
        }
        asm volatile("cp.async.commit_group;");
    };

    load_stage(0, 0);
    load_stage(1, 64);
    load_stage(2, 128);

    for (int t = 0; t < nIter; t++) {
        const int b = t % 3;
        asm volatile("cp.async.wait_group 2;");
        __syncthreads();

        if (warp == 0 && elect_one()) {
            FENCE_ASYNC();
            uint32_t sbase = sb0 + b * TSTAGE_BYTES;
            uint64_t adh = MAKE_DESC(sbase);
            uint64_t adl = MAKE_DESC(sbase + 16384u);
            uint64_t bdh = MAKE_DESC(sbase + 32768u);
            uint64_t bdl = MAKE_DESC(sbase + 49152u);
            uint32_t en = (t > 0) ? 1u : 0u;
#pragma unroll
            for (int k = 0; k < 4; k++) {
                TC_MMA_F16(tmem, adh + k * 2, bdh + k * 2, IDESC_128, en);
                en = 1u;
                TC_MMA_F16(tmem, adh + k * 2, bdl + k * 2, IDESC_128, 1u);
                TC_MMA_F16(tmem, adl + k * 2, bdh + k * 2, IDESC_128, 1u);
            }
            TC_COMMIT(mb0 + b * 8);
        }

        const int tl = t + 3;
        if (tl < nIter) {
            const uint32_t wp = (uint32_t)((tl / 3 - 1) & 1);
            MBAR_WAIT(mb0 + b * 8, wp);
            load_stage(b, tl * 64);
        } else {
            asm volatile("cp.async.commit_group;");
        }
    }

    {
        const int tlast = nIter - 1;
        MBAR_WAIT(mb0 + (tlast % 3) * 8, (uint32_t)((tlast / 3) & 1));
    }
    TC_FENCE_AFTER();

    // epilogue: warp w -> subpartition rows (w&3)*32+lane, column half w>>2
    const int srow = blockRow + (warp & 3) * 32 + lane;
    const int chalf = (warp >> 2) * 64;
#pragma unroll
    for (int cb = 0; cb < 2; cb++) {
        const int col0 = chalf + cb * 32;
        uint32_t d[32];
        TC_LD_X32(d, tmem + col0);
        TC_WAIT_LD();
        float v[32];
#pragma unroll
        for (int j = 0; j < 32; j++) {
            float f = __uint_as_float(d[j]) * alpha;
            if (BIAS) f += bp[blockCol + col0 + j];
            if (RELU) f = fmaxf(f, 0.0f);
            v[j] = f;
        }
        TC_FENCE_BEFORE();
        if (SPLITOUT) {
#pragma unroll
            for (int j = 0; j < 16; j++) {
                uint32_t h, l;
                split2(v[2 * j], v[2 * j + 1], h, l);
                long long off = cOff + (long long)srow * N + blockCol + col0 + 2 * j;
                *(uint32_t*)(Ch + off) = h;
                *(uint32_t*)(Cl + off) = l;
            }
        } else {
#pragma unroll
            for (int j = 0; j < 8; j++) {
                float4 f4 = make_float4(v[4 * j], v[4 * j + 1], v[4 * j + 2], v[4 * j + 3]);
                *(float4*)(C + cOff + (long long)srow * N + blockCol + col0 + 4 * j) = f4;
            }
        }
    }

    __syncthreads();
    if (warp == 0) {
        TC_RELINQ();
        TC_DEALLOC(tmem, 128);
    }
#else
    // ===================== mma.sync fallback (compute_103) ==================
    const uint32_t sbase = smem_u32(smem);
    const int wm = warp >> 2;
    const int wn = warp & 3;

    const __nv_bfloat16* srcA[4];
    const __nv_bfloat16* srcB[4];
    uint32_t dstA[4], dstB[4];
#pragma unroll
    for (int i = 0; i < 4; i++) {
        int idx = i * 256 + tid;
        int row = idx >> 3;
        int sub = idx & 7;
        int part = sub >> 2;
        int cc = sub & 3;
        uint32_t chunk = (uint32_t)(((part << 2) | cc) ^ (row & 7));
        dstA[i] = (uint32_t)(row * 128) + (chunk << 4);
        dstB[i] = dstA[i] + 16384u;
        srcA[i] = (part ? Al : Ah) + (long long)(blockRow + row) * K + cc * 8;
        srcB[i] = (part ? Bl : Bh) + (long long)(blockCol + row) * K + cc * 8;
    }

    uint32_t aoff[4], boff[2];
    {
        int kh = lane >> 4;
#pragma unroll
        for (int mf = 0; mf < 4; mf++) {
            int r = wm * 64 + mf * 16 + (lane & 15);
            aoff[mf] = (uint32_t)(r * 128) + ((uint32_t)(kh ^ (r & 7)) << 4);
        }
        int khb = (lane >> 3) & 1;
#pragma unroll
        for (int ng = 0; ng < 2; ng++) {
            int n = wn * 32 + ng * 16 + ((lane >> 4) << 3) + (lane & 7);
            boff[ng] = (uint32_t)(n * 128) + ((uint32_t)(khb ^ (n & 7)) << 4) + 16384u;
        }
    }

    float acc[4][4][4];
#pragma unroll
    for (int a = 0; a < 4; a++)
#pragma unroll
        for (int b = 0; b < 4; b++)
#pragma unroll
            for (int r = 0; r < 4; r++) acc[a][b][r] = 0.0f;

    const int nIter = K / 32;

    auto load_stage = [&](int s, int k0) {
        uint32_t base = sbase + s * FB_STAGE_BYTES;
#pragma unroll
        for (int i = 0; i < 4; i++) cp16(base + dstA[i], srcA[i] + k0);
#pragma unroll
        for (int i = 0; i < 4; i++) cp16(base + dstB[i], srcB[i] + k0);
        asm volatile("cp.async.commit_group;");
    };

#pragma unroll
    for (int s = 0; s < 2; s++) load_stage(s, s * 32);

    for (int t = 0; t < nIter; t++) {
        asm volatile("cp.async.wait_group 1;");
        __syncthreads();
        const int s = t % 3;
        const int tn = t + 2;
        if (tn < nIter) load_stage(tn % 3, tn * 32);
        else asm volatile("cp.async.commit_group;");

        const uint32_t stBase = sbase + s * FB_STAGE_BYTES;
#pragma unroll
        for (int ks = 0; ks < 2; ks++) {
            const uint32_t kx = ks ? 32u : 0u;
            uint32_t ah[4][4], al[4][4], bh[4][2], bl[4][2];
#pragma unroll
            for (int mf = 0; mf < 4; mf++) {
                uint32_t ad = stBase + (aoff[mf] ^ kx);
                LDSM4(ah[mf][0], ah[mf][1], ah[mf][2], ah[mf][3], ad);
                LDSM4(al[mf][0], al[mf][1], al[mf][2], al[mf][3], ad ^ 64u);
            }
#pragma unroll
            for (int ng = 0; ng < 2; ng++) {
                uint32_t bd = stBase + (boff[ng] ^ kx);
                LDSM4(bh[2 * ng][0], bh[2 * ng][1], bh[2 * ng + 1][0],
                      bh[2 * ng + 1][1], bd);
                LDSM4(bl[2 * ng][0], bl[2 * ng][1], bl[2 * ng + 1][0],
                      bl[2 * ng + 1][1], bd ^ 64u);
            }
#pragma unroll
            for (int mf = 0; mf < 4; mf++)
#pragma unroll
                for (int nf = 0; nf < 4; nf++) {
                    MMA_SYNC_BF16(acc[mf][nf], ah[mf], bh[nf]);
                    MMA_SYNC_BF16(acc[mf][nf], ah[mf], bl[nf]);
                    MMA_SYNC_BF16(acc[mf][nf], al[mf], bh[nf]);
                }
        }
        __syncthreads();
    }

#pragma unroll
    for (int mf = 0; mf < 4; mf++) {
        int row = blockRow + wm * 64 + mf * 16 + (lane >> 2);
#pragma unroll
        for (int nf = 0; nf < 4; nf++) {
            int col = blockCol + wn * 32 + nf * 8 + (lane & 3) * 2;
            float2 v0, v1;
            v0.x = acc[mf][nf][0] * alpha;
            v0.y = acc[mf][nf][1] * alpha;
            v1.x = acc[mf][nf][2] * alpha;
            v1.y = acc[mf][nf][3] * alpha;
            if (BIAS) {
                float b0 = bp[col], b1 = bp[col + 1];
                v0.x += b0; v0.y += b1;
                v1.x += b0; v1.y += b1;
            }
            if (RELU) {
                v0.x = fmaxf(v0.x, 0.f); v0.y = fmaxf(v0.y, 0.f);
                v1.x = fmaxf(v1.x, 0.f); v1.y = fmaxf(v1.y, 0.f);
            }
            if (SPLITOUT) {
                uint32_t h, l;
                split2(v0.x, v0.y, h, l);
                *(uint32_t*)(Ch + cOff + (long long)row * N + col) = h;
                *(uint32_t*)(Cl + cOff + (long long)row * N + col) = l;
                split2(v1.x, v1.y, h, l);
                *(uint32_t*)(Ch + cOff + (long long)(row + 8) * N + col) = h;
                *(uint32_t*)(Cl + cOff + (long long)(row + 8) * N + col) = l;
            } else {
                *(float2*)(C + cOff + (long long)row * N + col) = v0;
                *(float2*)(C + cOff + (long long)(row + 8) * N + col) = v1;
            }
        }
    }
#endif
}

// ---------------- row softmax + split write ----------------
__global__ __launch_bounds__(256) void softmax_kernel() {
    long long row = blockIdx.x;
    float* p = g_scores + row * SEQ;
    const int tid = threadIdx.x;

    float4 a = ((const float4*)p)[tid * 2 + 0];
    float4 b = ((const float4*)p)[tid * 2 + 1];

    float m = fmaxf(fmaxf(fmaxf(a.x, a.y), fmaxf(a.z, a.w)),
                    fmaxf(fmaxf(b.x, b.y), fmaxf(b.z, b.w)));
    __shared__ float red[256];
    red[tid] = m;
    __syncthreads();
    for (int o = 128; o > 0; o >>= 1) {
        if (tid < o) red[tid] = fmaxf(red[tid], red[tid + o]);
        __syncthreads();
    }
    m = red[0];
    __syncthreads();

    a.x = expf(a.x - m); a.y = expf(a.y - m); a.z = expf(a.z - m); a.w = expf(a.w - m);
    b.x = expf(b.x - m); b.y = expf(b.y - m); b.z = expf(b.z - m); b.w = expf(b.w - m);
    float s = a.x + a.y + a.z + a.w + b.x + b.y + b.z + b.w;
    red[tid] = s;
    __syncthreads();
    for (int o = 128; o > 0; o >>= 1) {
        if (tid < o) red[tid] += red[tid + o];
        __syncthreads();
    }
    float inv = 1.0f / red[0];
    a.x *= inv; a.y *= inv; a.z *= inv; a.w *= inv;
    b.x *= inv; b.y *= inv; b.z *= inv; b.w *= inv;

    uint32_t h0, l0, h1, l1, h2, l2, h3, l3;
    split2(a.x, a.y, h0, l0);
    split2(a.z, a.w, h1, l1);
    split2(b.x, b.y, h2, l2);
    split2(b.z, b.w, h3, l3);
    ((uint4*)(g_ah_ + row * SEQ))[tid] = make_uint4(h0, h1, h2, h3);
    ((uint4*)(g_al_ + row * SEQ))[tid] = make_uint4(l0, l1, l2, l3);
}

// -------- head-sum + residual; double (sum, sumsq) partials --------
__global__ __launch_bounds__(256) void residual_reduce_kernel() {
    const int tid = threadIdx.x;
    long long base = (long long)blockIdx.x * 1024;
    double s = 0.0, ss = 0.0;
#pragma unroll
    for (int it = 0; it < 4; it++) {
        long long idx = base + tid + it * 256;
        float acc = g_x[idx];
#pragma unroll
        for (int h = 0; h < NH; h++) acc += g_o[(long long)h * SEQ * DIM + idx];
        g_z[idx] = acc;
        s += acc;
        ss += (double)acc * acc;
    }
    __shared__ double sh[256], sh2[256];
    sh[tid] = s; sh2[tid] = ss;
    __syncthreads();
    for (int o = 128; o > 0; o >>= 1) {
        if (tid < o) { sh[tid] += sh[tid + o]; sh2[tid] += sh2[tid + o]; }
        __syncthreads();
    }
    if (tid == 0) {
        g_part[blockIdx.x * 2 + 0] = sh[0];
        g_part[blockIdx.x * 2 + 1] = sh2[0];
    }
}

__global__ __launch_bounds__(256) void finalize_stats_kernel() {
    const int tid = threadIdx.x;
    double s = 0.0, ss = 0.0;
    for (int i = tid; i < 2048; i += 256) {
        s += g_part[2 * i + 0];
        ss += g_part[2 * i + 1];
    }
    __shared__ double sh[256], sh2[256];
    sh[tid] = s; sh2[tid] = ss;
    __syncthreads();
    for (int o = 128; o > 0; o >>= 1) {
        if (tid < o) { sh[tid] += sh[tid + o]; sh2[tid] += sh2[tid + o]; }
        __syncthreads();
    }
    if (tid == 0) {
        double n = (double)SEQ * DIM;
        double mean = sh[0] / n;
        double var = sh2[0] / n - mean * mean;
        g_stats[0] = (float)mean;
        g_stats[1] = (float)(1.0 / sqrt(var + (double)EPSV));
    }
}

__global__ __launch_bounds__(256) void normalize_kernel() {
    float mean = g_stats[0];
    float inv = g_stats[1];
    long long idx = ((long long)blockIdx.x * 256 + threadIdx.x) * 4;
    float4 v = *(const float4*)&g_z[idx];
    v.x = (v.x - mean) * inv;
    v.y = (v.y - mean) * inv;
    v.z = (v.z - mean) * inv;
    v.w = (v.w - mean) * inv;
    uint32_t h0, l0, h1, l1;
    split2(v.x, v.y, h0, l0);
    split2(v.z, v.w, h1, l1);
    *(uint2*)(g_znh + idx) = make_uint2(h0, h1);
    *(uint2*)(g_znl + idx) = make_uint2(l0, l1);
}

// --------------------------------- launch ------------------------------------
extern "C" void kernel_launch(void* const* d_in, const int* in_sizes, int n_in,
                              void* d_out, int out_size) {
    const int* tokens = (const int*)d_in[0];
    const float* emb = (const float*)d_in[1];
    const float* Wq = (const float*)d_in[2];
    const float* bq = (const float*)d_in[3];
    const float* Wk = (const float*)d_in[4];
    const float* bk = (const float*)d_in[5];
    const float* Wv = (const float*)d_in[6];
    const float* bv = (const float*)d_in[7];
    const float* W1 = (const float*)d_in[8];
    const float* b1 = (const float*)d_in[9];
    const float* W2 = (const float*)d_in[10];
    const float* b2 = (const float*)d_in[11];
    float* out = (float*)d_out;

    float *x, *v, *sc, *o;
    __nv_bfloat16 *xh, *xl, *qh, *ql, *kh, *kl, *vth, *vtl, *ah, *al;
    __nv_bfloat16 *znh, *znl, *ffhh, *ffhl;
    __nv_bfloat16 *wqth, *wqtl, *wkth, *wktl, *wvth, *wvtl, *w1th, *w1tl, *w2th, *w2tl;
    cudaGetSymbolAddress((void**)&x, g_x);
    cudaGetSymbolAddress((void**)&v, g_v);
    cudaGetSymbolAddress((void**)&sc, g_scores);
    cudaGetSymbolAddress((void**)&o, g_o);
    cudaGetSymbolAddress((void**)&xh, g_xh);
    cudaGetSymbolAddress((void**)&xl, g_xl);
    cudaGetSymbolAddress((void**)&qh, g_qh);
    cudaGetSymbolAddress((void**)&ql, g_ql);
    cudaGetSymbolAddress((void**)&kh, g_kh);
    cudaGetSymbolAddress((void**)&kl, g_kl);
    cudaGetSymbolAddress((void**)&vth, g_vth);
    cudaGetSymbolAddress((void**)&vtl, g_vtl);
    cudaGetSymbolAddress((void**)&ah, g_ah_);
    cudaGetSymbolAddress((void**)&al, g_al_);
    cudaGetSymbolAddress((void**)&znh, g_znh);
    cudaGetSymbolAddress((void**)&znl, g_znl);
    cudaGetSymbolAddress((void**)&ffhh, g_ffhh);
    cudaGetSymbolAddress((void**)&ffhl, g_ffhl);
    cudaGetSymbolAddress((void**)&wqth, g_wqth);
    cudaGetSymbolAddress((void**)&wqtl, g_wqtl);
    cudaGetSymbolAddress((void**)&wkth, g_wkth);
    cudaGetSymbolAddress((void**)&wktl, g_wktl);
    cudaGetSymbolAddress((void**)&wvth, g_wvth);
    cudaGetSymbolAddress((void**)&wvtl, g_wvtl);
    cudaGetSymbolAddress((void**)&w1th, g_w1th);
    cudaGetSymbolAddress((void**)&w1tl, g_w1tl);
    cudaGetSymbolAddress((void**)&w2th, g_w2th);
    cudaGetSymbolAddress((void**)&w2tl, g_w2tl);

    cudaFuncSetAttribute(tgemm<true, false, true>,
                         cudaFuncAttributeMaxDynamicSharedMemorySize, TSMEM_BYTES);
    cudaFuncSetAttribute(tgemm<true, false, false>,
                         cudaFuncAttributeMaxDynamicSharedMemorySize, TSMEM_BYTES);
    cudaFuncSetAttribute(tgemm<false, false, false>,
                         cudaFuncAttributeMaxDynamicSharedMemorySize, TSMEM_BYTES);
    cudaFuncSetAttribute(tgemm<true, true, true>,
                         cudaFuncAttributeMaxDynamicSharedMemorySize, TSMEM_BYTES);

    embed_pe_kernel<<<SEQ, 256>>>(tokens, emb);
    split_kernel<<<SEQ * DIM / 1024, 256>>>(x, xh, xl);

    {
        dim3 tb(32, 8);
        tsplit_kernel<<<dim3(32, 32, 8), tb>>>(Wq, wqth, wqtl, DIM, DIM,
                                               (long long)DIM * DIM, (long long)DIM * DIM);
        tsplit_kernel<<<dim3(32, 32, 8), tb>>>(Wk, wkth, wktl, DIM, DIM,
                                               (long long)DIM * DIM, (long long)DIM * DIM);
        tsplit_kernel<<<dim3(32, 32, 8), tb>>>(Wv, wvth, wvtl, DIM, DIM,
                                               (long long)DIM * DIM, (long long)DIM * DIM);
        tsplit_kernel<<<dim3(DFF / 32, DIM / 32, 1), tb>>>(W1, w1th, w1tl, DIM, DFF, 0, 0);
        tsplit_kernel<<<dim3(DIM / 32, DFF / 32, 1), tb>>>(W2, w2th, w2tl, DFF, DIM, 0, 0);
    }

    // Q,K projections -> split outputs; V -> fp32 then transpose-split
    {
        dim3 grid(DIM / 128, SEQ / 128, NH);
        tgemm<true, false, true><<<grid, 256, TSMEM_BYTES>>>(
            xh, xl, wqth, wqtl, bq, nullptr, qh, ql, SEQ, DIM, DIM,
            0, (long long)DIM * DIM, DIM, (long long)SEQ * DIM, 1.0f);
        tgemm<true, false, true><<<grid, 256, TSMEM_BYTES>>>(
            xh, xl, wkth, wktl, bk, nullptr, kh, kl, SEQ, DIM, DIM,
            0, (long long)DIM * DIM, DIM, (long long)SEQ * DIM, 1.0f);
        tgemm<true, false, false><<<grid, 256, TSMEM_BYTES>>>(
            xh, xl, wvth, wvtl, bv, v, nullptr, nullptr, SEQ, DIM, DIM,
            0, (long long)DIM * DIM, DIM, (long long)SEQ * DIM, 1.0f);
        tsplit_kernel<<<dim3(DIM / 32, SEQ / 32, NH), dim3(32, 8)>>>(
            v, vth, vtl, SEQ, DIM, (long long)SEQ * DIM, (long long)SEQ * DIM);
    }

    // scores = Q @ K^T / 32
    {
        dim3 grid(SEQ / 128, SEQ / 128, NH);
        tgemm<false, false, false><<<grid, 256, TSMEM_BYTES>>>(
            qh, ql, kh, kl, nullptr, sc, nullptr, nullptr, SEQ, SEQ, DIM,
            (long long)SEQ * DIM, (long long)SEQ * DIM, 0,
            (long long)SEQ * SEQ, 1.0f / 32.0f);
    }

    softmax_kernel<<<NH * SEQ, 256>>>();

    // O = attn @ V
    {
        dim3 grid(DIM / 128, SEQ / 128, NH);
        tgemm<false, false, false><<<grid, 256, TSMEM_BYTES>>>(
            ah, al, vth, vtl, nullptr, o, nullptr, nullptr, SEQ, DIM, SEQ,
            (long long)SEQ * SEQ, (long long)SEQ * DIM, 0,
            (long long)SEQ * DIM, 1.0f);
    }

    residual_reduce_kernel<<<2048, 256>>>();
    finalize_stats_kernel<<<1, 256>>>();
    normalize_kernel<<<2048, 256>>>();

    // FFN
    {
        dim3 grid(DFF / 128, SEQ / 128, 1);
        tgemm<true, true, true><<<grid, 256, TSMEM_BYTES>>>(
            znh, znl, w1th, w1tl, b1, nullptr, ffhh, ffhl, SEQ, DFF, DIM,
            0, 0, 0, 0, 1.0f);
    }
    {
        dim3 grid(DIM / 128, SEQ / 128, 1);
        tgemm<true, false, false><<<grid, 256, TSMEM_BYTES>>>(
            ffhh, ffhl, w2th, w2tl, b2, out, nullptr, nullptr, SEQ, DIM, DFF,
            0, 0, 0, 0, 1.0f);
    }
}

// round 6
// speedup vs baseline: 5.2499x; 1.0241x over previous
#include <cuda_runtime.h>
#include <cuda_bf16.h>
#include <math.h>
#include <stdint.h>

#define SEQ 2048
#define DIM 1024
#define NH 8
#define DFF 3072
#define EPSV 1e-5f

// tcgen05 only exists on the arch-specific target pass (sm_103a / sm_100a).
#if defined(__CUDA_ARCH_FEAT_SM103_ALL) || defined(__CUDA_ARCH_FEAT_SM100_ALL)
#define HAS_TCGEN05 1
#else
#define HAS_TCGEN05 0
#endif

// ---------------- static device scratch ----------------
__device__ __align__(128) float g_x[SEQ * DIM];
__device__ __align__(128) __nv_bfloat16 g_xh[SEQ * DIM], g_xl[SEQ * DIM];
__device__ __align__(128) __nv_bfloat16 g_qh[NH * SEQ * DIM], g_ql[NH * SEQ * DIM];
__device__ __align__(128) __nv_bfloat16 g_kh[NH * SEQ * DIM], g_kl[NH * SEQ * DIM];
__device__ __align__(128) __nv_bfloat16 g_vth[NH * SEQ * DIM], g_vtl[NH * SEQ * DIM];
__device__ __align__(128) float g_scores[(size_t)NH * SEQ * SEQ];
__device__ __align__(128) __nv_bfloat16 g_ah_[(size_t)NH * SEQ * SEQ];
__device__ __align__(128) __nv_bfloat16 g_al_[(size_t)NH * SEQ * SEQ];
__device__ __align__(128) float g_o[NH * SEQ * DIM];
__device__ __align__(128) float g_z[SEQ * DIM];
__device__ __align__(128) __nv_bfloat16 g_znh[SEQ * DIM], g_znl[SEQ * DIM];
__device__ __align__(128) __nv_bfloat16 g_ffhh[SEQ * DFF], g_ffhl[SEQ * DFF];
__device__ __align__(128) __nv_bfloat16 g_wqth[NH * DIM * DIM], g_wqtl[NH * DIM * DIM];
__device__ __align__(128) __nv_bfloat16 g_wkth[NH * DIM * DIM], g_wktl[NH * DIM * DIM];
__device__ __align__(128) __nv_bfloat16 g_wvth[NH * DIM * DIM], g_wvtl[NH * DIM * DIM];
__device__ __align__(128) __nv_bfloat16 g_w1th[DFF * DIM], g_w1tl[DFF * DIM];
__device__ __align__(128) __nv_bfloat16 g_w2th[DIM * DFF], g_w2tl[DIM * DFF];
__device__ double g_part[2 * 2048];
__device__ float g_stats[2];

// ---------------- helpers ----------------
__device__ __forceinline__ void split2(float x, float y, uint32_t& h, uint32_t& l) {
    __nv_bfloat16 bx = __float2bfloat16_rn(x);
    __nv_bfloat16 by = __float2bfloat16_rn(y);
    __nv_bfloat162 hv;
    hv.x = bx; hv.y = by;
    h = *reinterpret_cast<uint32_t*>(&hv);
    __nv_bfloat162 lv = __floats2bfloat162_rn(x - __bfloat162float(bx),
                                              y - __bfloat162float(by));
    l = *reinterpret_cast<uint32_t*>(&lv);
}

__device__ __forceinline__ void cp16(uint32_t d, const void* s) {
    asm volatile("cp.async.cg.shared.global [%0], [%1], 16;" :: "r"(d), "l"(s));
}

__device__ __forceinline__ uint32_t smem_u32(const void* p) {
    uint32_t a;
    asm("{ .reg .u64 t; cvta.to.shared.u64 t, %1; cvt.u32.u64 %0, t; }"
        : "=r"(a) : "l"(p));
    return a;
}

__device__ __forceinline__ uint32_t elect_one() {
    uint32_t pred;
    asm volatile(
        "{\n\t.reg .pred p;\n\telect.sync _|p, 0xFFFFFFFF;\n\t"
        "selp.b32 %0, 1, 0, p;\n\t}" : "=r"(pred));
    return pred;
}

#define MBAR_INIT(addr, cnt) \
    asm volatile("mbarrier.init.shared.b64 [%0], %1;" :: "r"(addr), "r"(cnt) : "memory")

#define MBAR_WAIT(addr, par) do {                                              \
    uint32_t _m = (addr), _p = (par), _d;                                      \
    asm volatile(                                                              \
        "{\n\t.reg .pred p;\n\t"                                               \
        "mbarrier.try_wait.parity.acquire.cta.shared::cta.b64 p, [%1], %2;\n\t" \
        "selp.b32 %0, 1, 0, p;\n\t}" : "=r"(_d) : "r"(_m), "r"(_p) : "memory"); \
    if (!_d) {                                                                 \
        asm volatile(                                                          \
            "{\n\t.reg .pred P1;\n\t"                                          \
            "WL_%=:\n\t"                                                       \
            "mbarrier.try_wait.parity.acquire.cta.shared::cta.b64 P1, [%0], %1, 0x989680;\n\t" \
            "@P1 bra.uni WD_%=;\n\tbra.uni WL_%=;\n\tWD_%=:\n\t}"              \
            :: "r"(_m), "r"(_p) : "memory");                                   \
    }                                                                          \
} while (0)

// tcgen05 macros
#define TC_ALLOC(addr, n)                                                      \
    asm volatile("tcgen05.alloc.cta_group::1.sync.aligned.shared::cta.b32 [%0], %1;" \
                 :: "r"(addr), "r"(n) : "memory")
#define TC_DEALLOC(t, n) \
    asm volatile("tcgen05.dealloc.cta_group::1.sync.aligned.b32 %0, %1;" :: "r"(t), "r"(n))
#define TC_RELINQ() \
    asm volatile("tcgen05.relinquish_alloc_permit.cta_group::1.sync.aligned;")
#define TC_FENCE_AFTER() asm volatile("tcgen05.fence::after_thread_sync;" ::: "memory")
#define TC_FENCE_BEFORE() asm volatile("tcgen05.fence::before_thread_sync;" ::: "memory")
#define TC_WAIT_LD() asm volatile("tcgen05.wait::ld.sync.aligned;" ::: "memory")
#define FENCE_ASYNC() asm volatile("fence.proxy.async.shared::cta;" ::: "memory")
#define TC_COMMIT(addr)                                                        \
    asm volatile(                                                              \
        "tcgen05.commit.cta_group::1.mbarrier::arrive::one.shared::cluster.b64 [%0];" \
        :: "r"(addr) : "memory")
#define TC_MMA_F16(d, a, b, idesc, en)                                         \
    asm volatile(                                                              \
        "{\n\t.reg .pred p;\n\tsetp.ne.u32 p, %4, 0;\n\t"                      \
        "tcgen05.mma.cta_group::1.kind::f16 [%0], %1, %2, %3, {%5,%5,%5,%5}, p;\n\t}" \
        :: "r"(d), "l"(a), "l"(b), "r"(idesc), "r"(en), "r"(0u) : "memory")
#define TC_LD_X32(r, a)                                                        \
    asm volatile(                                                              \
        "tcgen05.ld.sync.aligned.32x32b.x32.b32 "                              \
        "{%0, %1, %2, %3, %4, %5, %6, %7, "                                    \
        " %8, %9, %10, %11, %12, %13, %14, %15, "                              \
        " %16, %17, %18, %19, %20, %21, %22, %23, "                            \
        " %24, %25, %26, %27, %28, %29, %30, %31}, [%32];"                     \
        : "=r"((r)[0]),  "=r"((r)[1]),  "=r"((r)[2]),  "=r"((r)[3]),           \
          "=r"((r)[4]),  "=r"((r)[5]),  "=r"((r)[6]),  "=r"((r)[7]),           \
          "=r"((r)[8]),  "=r"((r)[9]),  "=r"((r)[10]), "=r"((r)[11]),          \
          "=r"((r)[12]), "=r"((r)[13]), "=r"((r)[14]), "=r"((r)[15]),          \
          "=r"((r)[16]), "=r"((r)[17]), "=r"((r)[18]), "=r"((r)[19]),          \
          "=r"((r)[20]), "=r"((r)[21]), "=r"((r)[22]), "=r"((r)[23]),          \
          "=r"((r)[24]), "=r"((r)[25]), "=r"((r)[26]), "=r"((r)[27]),          \
          "=r"((r)[28]), "=r"((r)[29]), "=r"((r)[30]), "=r"((r)[31])           \
        : "r"(a))

// SW128 K-major descriptor: LBO=1 (16B), SBO=64 (1024B), version=1, layout=2
#define DESC_BASE_SW128                                                        \
    ((uint64_t(2) << 61) | (uint64_t(1) << 46) | (uint64_t(64) << 32) |        \
     (uint64_t(1) << 16))
#define MAKE_DESC(addr) (DESC_BASE_SW128 | ((uint64_t)((addr) >> 4) & 0x3FFF))
// f32 acc, bf16 a/b, M=128, N=256
#define IDESC_N256 0x8400490u

// ---------------- embedding + PE ----------------
__global__ void embed_pe_kernel(const int* __restrict__ tokens,
                                const float* __restrict__ emb) {
    int s = blockIdx.x;
    int tok = tokens[s];
    const float* erow = emb + (long long)tok * DIM;
    for (int d = threadIdx.x; d < DIM; d += blockDim.x) {
        int e = d & ~1;
        float denom = powf(10000.0f, (float)e / (float)DIM);
        float angle = (float)s / denom;
        float pe = (d & 1) ? (float)cos((double)angle) : (float)sin((double)angle);
        g_x[s * DIM + d] = erow[d] + pe;
    }
}

// ---------------- elementwise split fp32 -> bf16 hi/lo ----------------
__global__ __launch_bounds__(256) void split_kernel(const float* __restrict__ in,
                                                    __nv_bfloat16* __restrict__ oh,
                                                    __nv_bfloat16* __restrict__ ol) {
    long long i = ((long long)blockIdx.x * 256 + threadIdx.x) * 4;
    float4 v = *(const float4*)(in + i);
    uint32_t h0, l0, h1, l1;
    split2(v.x, v.y, h0, l0);
    split2(v.z, v.w, h1, l1);
    *(uint2*)(oh + i) = make_uint2(h0, h1);
    *(uint2*)(ol + i) = make_uint2(l0, l1);
}

// ---------------- transpose + split (weights) ----------------
__global__ __launch_bounds__(256) void tsplit_kernel(
    const float* __restrict__ in, __nv_bfloat16* __restrict__ oh,
    __nv_bfloat16* __restrict__ ol, int R, int C, long long sIn, long long sOut) {
    __shared__ float t[32][33];
    int z = blockIdx.z;
    in += (long long)z * sIn;
    oh += (long long)z * sOut;
    ol += (long long)z * sOut;
    int c0 = blockIdx.x * 32, r0 = blockIdx.y * 32;
    int tx = threadIdx.x, ty = threadIdx.y;
#pragma unroll
    for (int j = 0; j < 4; j++)
        t[ty + j * 8][tx] = in[(long long)(r0 + ty + j * 8) * C + c0 + tx];
    __syncthreads();
#pragma unroll
    for (int j = 0; j < 4; j++) {
        float v = t[tx][ty + j * 8];
        int orow = c0 + ty + j * 8;
        int ocol = r0 + tx;
        __nv_bfloat16 h = __float2bfloat16_rn(v);
        oh[(long long)orow * R + ocol] = h;
        ol[(long long)orow * R + ocol] = __float2bfloat16_rn(v - __bfloat162float(h));
    }
}

// =================== tcgen05 bf16-split GEMM (TN), tile 128x256 =============
// C[M,N] = alpha * A[M,K] @ B[N,K]^T (+bias)(+relu), 3-term bf16 hi/lo.
// OUTMODE: 0 = fp32 C, 1 = split hi/lo bf16, 2 = TRANSPOSED split hi/lo (C^T).
// 256 threads. K-chunk 64, 2-stage cp.async ring, 256-col TMEM accumulator.

#define TSTAGE_BYTES 98304                      // Ah16K Al16K Bh32K Bl32K
#define TSMEM_BYTES (2 * TSTAGE_BYTES + 1024)   // 197632

template <bool BIAS, bool RELU, int OUTMODE>
__global__ __launch_bounds__(256) void tgemm(
    const __nv_bfloat16* __restrict__ Ah, const __nv_bfloat16* __restrict__ Al,
    const __nv_bfloat16* __restrict__ Bh, const __nv_bfloat16* __restrict__ Bl,
    const float* __restrict__ bias, float* __restrict__ C,
    __nv_bfloat16* __restrict__ Ch, __nv_bfloat16* __restrict__ Cl,
    int M, int N, int K,
    long long sA, long long sB, long long sBias, long long sC, float alpha) {
    extern __shared__ char smem[];

    const int z = blockIdx.z;
    Ah += (long long)z * sA; Al += (long long)z * sA;
    Bh += (long long)z * sB; Bl += (long long)z * sB;
    const float* bp = BIAS ? (bias + (long long)z * sBias) : nullptr;
    const long long cOff = (long long)z * sC;

    const int tid = threadIdx.x;
    const int lane = tid & 31;
    const int warp = tid >> 5;
    const int blockRow = blockIdx.y * 128;
    const int blockCol = blockIdx.x * 256;

#if HAS_TCGEN05
    __shared__ __align__(8) unsigned long long s_mbar[2];
    __shared__ uint32_t s_tmem[1];
    const uint32_t sb0 = (smem_u32(smem) + 1023u) & ~1023u;
    const uint32_t mb0 = smem_u32(s_mbar);

    if (warp == 0) TC_ALLOC(smem_u32(s_tmem), 256);
    if (tid == 0) {
        MBAR_INIT(mb0 + 0, 1);
        MBAR_INIT(mb0 + 8, 1);
    }
    __syncthreads();
    const uint32_t tmem = s_tmem[0];

    const int nIter = K / 64;

    auto load_stage = [&](int buf, int k0) {
        uint32_t base = sb0 + buf * TSTAGE_BYTES;
        // A: 128 rows x (hi,lo): 2048 cp16 -> 8 per thread
#pragma unroll
        for (int i = 0; i < 8; i++) {
            int idx = i * 256 + tid;
            int part = idx >> 10;          // 0 hi, 1 lo
            int r = (idx >> 3) & 127;
            int c = idx & 7;
            uint32_t d0 = base + (uint32_t)(part * 16384) + (uint32_t)(r * 128) +
                          ((uint32_t)(c ^ (r & 7)) << 4);
            const __nv_bfloat16* src = (part ? Al : Ah);
            cp16(d0, src + (long long)(blockRow + r) * K + k0 + c * 8);
        }
        // B: 256 rows x (hi,lo): 4096 cp16 -> 16 per thread
#pragma unroll
        for (int i = 0; i < 16; i++) {
            int idx = i * 256 + tid;
            int part = idx >> 11;
            int r = (idx >> 3) & 255;
            int c = idx & 7;
            uint32_t d0 = base + 32768u + (uint32_t)(part * 32768) +
                          (uint32_t)(r * 128) + ((uint32_t)(c ^ (r & 7)) << 4);
            const __nv_bfloat16* src = (part ? Bl : Bh);
            cp16(d0, src + (long long)(blockCol + r) * K + k0 + c * 8);
        }
        asm volatile("cp.async.commit_group;");
    };

    load_stage(0, 0);
    load_stage(1, 64);

    for (int t = 0; t < nIter; t++) {
        const int b = t & 1;
        asm volatile("cp.async.wait_group 1;");
        __syncthreads();

        if (warp == 0 && elect_one()) {
            FENCE_ASYNC();
            uint32_t sbase = sb0 + b * TSTAGE_BYTES;
            uint64_t adh = MAKE_DESC(sbase);
            uint64_t adl = MAKE_DESC(sbase + 16384u);
            uint64_t bdh = MAKE_DESC(sbase + 32768u);
            uint64_t bdl = MAKE_DESC(sbase + 65536u);
            uint32_t en = (t > 0) ? 1u : 0u;
#pragma unroll
            for (int k = 0; k < 4; k++) {
                TC_MMA_F16(tmem, adh + k * 2, bdh + k * 2, IDESC_N256, en);
                en = 1u;
                TC_MMA_F16(tmem, adh + k * 2, bdl + k * 2, IDESC_N256, 1u);
                TC_MMA_F16(tmem, adl + k * 2, bdh + k * 2, IDESC_N256, 1u);
            }
            TC_COMMIT(mb0 + b * 8);
        }

        if (t + 2 < nIter) {
            MBAR_WAIT(mb0 + b * 8, (uint32_t)((t >> 1) & 1));
            load_stage(b, (t + 2) * 64);
        } else {
            asm volatile("cp.async.commit_group;");
        }
    }

    {
        const int tlast = nIter - 1;
        MBAR_WAIT(mb0 + (tlast & 1) * 8, (uint32_t)((tlast >> 1) & 1));
    }
    TC_FENCE_AFTER();

    // epilogue: warp w -> rows (w&3)*32+lane, column half (w>>2)*128
    const int srow = blockRow + (warp & 3) * 32 + lane;
    const int chalf = (warp >> 2) * 128;
#pragma unroll
    for (int cb = 0; cb < 4; cb++) {
        const int col0 = chalf + cb * 32;
        uint32_t d[32];
        TC_LD_X32(d, tmem + col0);
        TC_WAIT_LD();
        float v[32];
#pragma unroll
        for (int j = 0; j < 32; j++) {
            float f = __uint_as_float(d[j]) * alpha;
            if (BIAS) f += bp[blockCol + col0 + j];
            if (RELU) f = fmaxf(f, 0.0f);
            v[j] = f;
        }
        TC_FENCE_BEFORE();
        if (OUTMODE == 1) {
#pragma unroll
            for (int j = 0; j < 16; j++) {
                uint32_t h, l;
                split2(v[2 * j], v[2 * j + 1], h, l);
                long long off = cOff + (long long)srow * N + blockCol + col0 + 2 * j;
                *(uint32_t*)(Ch + off) = h;
                *(uint32_t*)(Cl + off) = l;
            }
        } else if (OUTMODE == 2) {
            // transposed split: C^T[col][row], leading dim M
#pragma unroll
            for (int j = 0; j < 32; j++) {
                int col = blockCol + col0 + j;
                __nv_bfloat16 h = __float2bfloat16_rn(v[j]);
                long long off = cOff + (long long)col * M + srow;
                Ch[off] = h;
                Cl[off] = __float2bfloat16_rn(v[j] - __bfloat162float(h));
            }
        } else {
#pragma unroll
            for (int j = 0; j < 8; j++) {
                float4 f4 = make_float4(v[4 * j], v[4 * j + 1], v[4 * j + 2], v[4 * j + 3]);
                *(float4*)(C + cOff + (long long)srow * N + blockCol + col0 + 4 * j) = f4;
            }
        }
    }

    __syncthreads();
    if (warp == 0) {
        TC_RELINQ();
        TC_DEALLOC(tmem, 256);
    }
#else
    // --------- naive fallback (compile-only target; never runs on GB300) ----
    for (int e = tid; e < 128 * 256; e += 256) {
        int r = e >> 8;
        int c = e & 255;
        int row = blockRow + r, col = blockCol + c;
        if (row >= M || col >= N) continue;
        float acc = 0.0f;
        for (int k = 0; k < K; k++) {
            float a = __bfloat162float(Ah[(long long)row * K + k]) +
                      __bfloat162float(Al[(long long)row * K + k]);
            float bb = __bfloat162float(Bh[(long long)col * K + k]) +
                       __bfloat162float(Bl[(long long)col * K + k]);
            acc += a * bb;
        }
        acc *= alpha;
        if (BIAS) acc += bp[col];
        if (RELU) acc = fmaxf(acc, 0.0f);
        if (OUTMODE == 1) {
            __nv_bfloat16 h = __float2bfloat16_rn(acc);
            long long off = cOff + (long long)row * N + col;
            Ch[off] = h;
            Cl[off] = __float2bfloat16_rn(acc - __bfloat162float(h));
        } else if (OUTMODE == 2) {
            __nv_bfloat16 h = __float2bfloat16_rn(acc);
            long long off = cOff + (long long)col * M + row;
            Ch[off] = h;
            Cl[off] = __float2bfloat16_rn(acc - __bfloat162float(h));
        } else {
            C[cOff + (long long)row * N + col] = acc;
        }
    }
#endif
}

// ---------------- row softmax + split write ----------------
__global__ __launch_bounds__(256) void softmax_kernel() {
    long long row = blockIdx.x;
    float* p = g_scores + row * SEQ;
    const int tid = threadIdx.x;

    float4 a = ((const float4*)p)[tid * 2 + 0];
    float4 b = ((const float4*)p)[tid * 2 + 1];

    float m = fmaxf(fmaxf(fmaxf(a.x, a.y), fmaxf(a.z, a.w)),
                    fmaxf(fmaxf(b.x, b.y), fmaxf(b.z, b.w)));
    __shared__ float red[256];
    red[tid] = m;
    __syncthreads();
    for (int o = 128; o > 0; o >>= 1) {
        if (tid < o) red[tid] = fmaxf(red[tid], red[tid + o]);
        __syncthreads();
    }
    m = red[0];
    __syncthreads();

    a.x = expf(a.x - m); a.y = expf(a.y - m); a.z = expf(a.z - m); a.w = expf(a.w - m);
    b.x = expf(b.x - m); b.y = expf(b.y - m); b.z = expf(b.z - m); b.w = expf(b.w - m);
    float s = a.x + a.y + a.z + a.w + b.x + b.y + b.z + b.w;
    red[tid] = s;
    __syncthreads();
    for (int o = 128; o > 0; o >>= 1) {
        if (tid < o) red[tid] += red[tid + o];
        __syncthreads();
    }
    float inv = 1.0f / red[0];
    a.x *= inv; a.y *= inv; a.z *= inv; a.w *= inv;
    b.x *= inv; b.y *= inv; b.z *= inv; b.w *= inv;

    uint32_t h0, l0, h1, l1, h2, l2, h3, l3;
    split2(a.x, a.y, h0, l0);
    split2(a.z, a.w, h1, l1);
    split2(b.x, b.y, h2, l2);
    split2(b.z, b.w, h3, l3);
    ((uint4*)(g_ah_ + row * SEQ))[tid] = make_uint4(h0, h1, h2, h3);
    ((uint4*)(g_al_ + row * SEQ))[tid] = make_uint4(l0, l1, l2, l3);
}

// -------- head-sum + residual; double (sum, sumsq) partials --------
__global__ __launch_bounds__(256) void residual_reduce_kernel() {
    const int tid = threadIdx.x;
    long long base = (long long)blockIdx.x * 1024;
    double s = 0.0, ss = 0.0;
#pragma unroll
    for (int it = 0; it < 4; it++) {
        long long idx = base + tid + it * 256;
        float acc = g_x[idx];
#pragma unroll
        for (int h = 0; h < NH; h++) acc += g_o[(long long)h * SEQ * DIM + idx];
        g_z[idx] = acc;
        s += acc;
        ss += (double)acc * acc;
    }
    __shared__ double sh[256], sh2[256];
    sh[tid] = s; sh2[tid] = ss;
    __syncthreads();
    for (int o = 128; o > 0; o >>= 1) {
        if (tid < o) { sh[tid] += sh[tid + o]; sh2[tid] += sh2[tid + o]; }
        __syncthreads();
    }
    if (tid == 0) {
        g_part[blockIdx.x * 2 + 0] = sh[0];
        g_part[blockIdx.x * 2 + 1] = sh2[0];
    }
}

__global__ __launch_bounds__(256) void finalize_stats_kernel() {
    const int tid = threadIdx.x;
    double s = 0.0, ss = 0.0;
    for (int i = tid; i < 2048; i += 256) {
        s += g_part[2 * i + 0];
        ss += g_part[2 * i + 1];
    }
    __shared__ double sh[256], sh2[256];
    sh[tid] = s; sh2[tid] = ss;
    __syncthreads();
    for (int o = 128; o > 0; o >>= 1) {
        if (tid < o) { sh[tid] += sh[tid + o]; sh2[tid] += sh2[tid + o]; }
        __syncthreads();
    }
    if (tid == 0) {
        double n = (double)SEQ * DIM;
        double mean = sh[0] / n;
        double var = sh2[0] / n - mean * mean;
        g_stats[0] = (float)mean;
        g_stats[1] = (float)(1.0 / sqrt(var + (double)EPSV));
    }
}

__global__ __launch_bounds__(256) void normalize_kernel() {
    float mean = g_stats[0];
    float inv = g_stats[1];
    long long idx = ((long long)blockIdx.x * 256 + threadIdx.x) * 4;
    float4 v = *(const float4*)&g_z[idx];
    v.x = (v.x - mean) * inv;
    v.y = (v.y - mean) * inv;
    v.z = (v.z - mean) * inv;
    v.w = (v.w - mean) * inv;
    uint32_t h0, l0, h1, l1;
    split2(v.x, v.y, h0, l0);
    split2(v.z, v.w, h1, l1);
    *(uint2*)(g_znh + idx) = make_uint2(h0, h1);
    *(uint2*)(g_znl + idx) = make_uint2(l0, l1);
}

// --------------------------------- launch ------------------------------------
extern "C" void kernel_launch(void* const* d_in, const int* in_sizes, int n_in,
                              void* d_out, int out_size) {
    const int* tokens = (const int*)d_in[0];
    const float* emb = (const float*)d_in[1];
    const float* Wq = (const float*)d_in[2];
    const float* bq = (const float*)d_in[3];
    const float* Wk = (const float*)d_in[4];
    const float* bk = (const float*)d_in[5];
    const float* Wv = (const float*)d_in[6];
    const float* bv = (const float*)d_in[7];
    const float* W1 = (const float*)d_in[8];
    const float* b1 = (const float*)d_in[9];
    const float* W2 = (const float*)d_in[10];
    const float* b2 = (const float*)d_in[11];
    float* out = (float*)d_out;

    float *x, *sc, *o;
    __nv_bfloat16 *xh, *xl, *qh, *ql, *kh, *kl, *vth, *vtl, *ah, *al;
    __nv_bfloat16 *znh, *znl, *ffhh, *ffhl;
    __nv_bfloat16 *wqth, *wqtl, *wkth, *wktl, *wvth, *wvtl, *w1th, *w1tl, *w2th, *w2tl;
    cudaGetSymbolAddress((void**)&x, g_x);
    cudaGetSymbolAddress((void**)&sc, g_scores);
    cudaGetSymbolAddress((void**)&o, g_o);
    cudaGetSymbolAddress((void**)&xh, g_xh);
    cudaGetSymbolAddress((void**)&xl, g_xl);
    cudaGetSymbolAddress((void**)&qh, g_qh);
    cudaGetSymbolAddress((void**)&ql, g_ql);
    cudaGetSymbolAddress((void**)&kh, g_kh);
    cudaGetSymbolAddress((void**)&kl, g_kl);
    cudaGetSymbolAddress((void**)&vth, g_vth);
    cudaGetSymbolAddress((void**)&vtl, g_vtl);
    cudaGetSymbolAddress((void**)&ah, g_ah_);
    cudaGetSymbolAddress((void**)&al, g_al_);
    cudaGetSymbolAddress((void**)&znh, g_znh);
    cudaGetSymbolAddress((void**)&znl, g_znl);
    cudaGetSymbolAddress((void**)&ffhh, g_ffhh);
    cudaGetSymbolAddress((void**)&ffhl, g_ffhl);
    cudaGetSymbolAddress((void**)&wqth, g_wqth);
    cudaGetSymbolAddress((void**)&wqtl, g_wqtl);
    cudaGetSymbolAddress((void**)&wkth, g_wkth);
    cudaGetSymbolAddress((void**)&wktl, g_wktl);
    cudaGetSymbolAddress((void**)&wvth, g_wvth);
    cudaGetSymbolAddress((void**)&wvtl, g_wvtl);
    cudaGetSymbolAddress((void**)&w1th, g_w1th);
    cudaGetSymbolAddress((void**)&w1tl, g_w1tl);
    cudaGetSymbolAddress((void**)&w2th, g_w2th);
    cudaGetSymbolAddress((void**)&w2tl, g_w2tl);

    cudaFuncSetAttribute(tgemm<true, false, 1>,
                         cudaFuncAttributeMaxDynamicSharedMemorySize, TSMEM_BYTES);
    cudaFuncSetAttribute(tgemm<true, false, 2>,
                         cudaFuncAttributeMaxDynamicSharedMemorySize, TSMEM_BYTES);
    cudaFuncSetAttribute(tgemm<false, false, 0>,
                         cudaFuncAttributeMaxDynamicSharedMemorySize, TSMEM_BYTES);
    cudaFuncSetAttribute(tgemm<true, true, 1>,
                         cudaFuncAttributeMaxDynamicSharedMemorySize, TSMEM_BYTES);
    cudaFuncSetAttribute(tgemm<true, false, 0>,
                         cudaFuncAttributeMaxDynamicSharedMemorySize, TSMEM_BYTES);

    embed_pe_kernel<<<SEQ, 256>>>(tokens, emb);
    split_kernel<<<SEQ * DIM / 1024, 256>>>(x, xh, xl);

    {
        dim3 tb(32, 8);
        tsplit_kernel<<<dim3(32, 32, 8), tb>>>(Wq, wqth, wqtl, DIM, DIM,
                                               (long long)DIM * DIM, (long long)DIM * DIM);
        tsplit_kernel<<<dim3(32, 32, 8), tb>>>(Wk, wkth, wktl, DIM, DIM,
                                               (long long)DIM * DIM, (long long)DIM * DIM);
        tsplit_kernel<<<dim3(32, 32, 8), tb>>>(Wv, wvth, wvtl, DIM, DIM,
                                               (long long)DIM * DIM, (long long)DIM * DIM);
        tsplit_kernel<<<dim3(DFF / 32, DIM / 32, 1), tb>>>(W1, w1th, w1tl, DIM, DFF, 0, 0);
        tsplit_kernel<<<dim3(DIM / 32, DFF / 32, 1), tb>>>(W2, w2th, w2tl, DFF, DIM, 0, 0);
    }

    // Q,K projections -> split outputs; V -> transposed split directly
    {
        dim3 grid(DIM / 256, SEQ / 128, NH);
        tgemm<true, false, 1><<<grid, 256, TSMEM_BYTES>>>(
            xh, xl, wqth, wqtl, bq, nullptr, qh, ql, SEQ, DIM, DIM,
            0, (long long)DIM * DIM, DIM, (long long)SEQ * DIM, 1.0f);
        tgemm<true, false, 1><<<grid, 256, TSMEM_BYTES>>>(
            xh, xl, wkth, wktl, bk, nullptr, kh, kl, SEQ, DIM, DIM,
            0, (long long)DIM * DIM, DIM, (long long)SEQ * DIM, 1.0f);
        tgemm<true, false, 2><<<grid, 256, TSMEM_BYTES>>>(
            xh, xl, wvth, wvtl, bv, nullptr, vth, vtl, SEQ, DIM, DIM,
            0, (long long)DIM * DIM, DIM, (long long)SEQ * DIM, 1.0f);
    }

    // scores = Q @ K^T / 32
    {
        dim3 grid(SEQ / 256, SEQ / 128, NH);
        tgemm<false, false, 0><<<grid, 256, TSMEM_BYTES>>>(
            qh, ql, kh, kl, nullptr, sc, nullptr, nullptr, SEQ, SEQ, DIM,
            (long long)SEQ * DIM, (long long)SEQ * DIM, 0,
            (long long)SEQ * SEQ, 1.0f / 32.0f);
    }

    softmax_kernel<<<NH * SEQ, 256>>>();

    // O = attn @ V   (B = V^T stored [D, S])
    {
        dim3 grid(DIM / 256, SEQ / 128, NH);
        tgemm<false, false, 0><<<grid, 256, TSMEM_BYTES>>>(
            ah, al, vth, vtl, nullptr, o, nullptr, nullptr, SEQ, DIM, SEQ,
            (long long)SEQ * SEQ, (long long)SEQ * DIM, 0,
            (long long)SEQ * DIM, 1.0f);
    }

    residual_reduce_kernel<<<2048, 256>>>();
    finalize_stats_kernel<<<1, 256>>>();
    normalize_kernel<<<2048, 256>>>();

    // FFN
    {
        dim3 grid(DFF / 256, SEQ / 128, 1);
        tgemm<true, true, 1><<<grid, 256, TSMEM_BYTES>>>(
            znh, znl, w1th, w1tl, b1, nullptr, ffhh, ffhl, SEQ, DFF, DIM,
            0, 0, 0, 0, 1.0f);
    }
    {
        dim3 grid(DIM / 256, SEQ / 128, 1);
        tgemm<true, false, 0><<<grid, 256, TSMEM_BYTES>>>(
            ffhh, ffhl, w2th, w2tl, b2, out, nullptr, nullptr, SEQ, DIM, DFF,
            0, 0, 0, 0, 1.0f);
    }
}